// round 5
// baseline (speedup 1.0000x reference)
#include <cuda_runtime.h>
#include <math.h>

#define NN    50000
#define EE    800000
#define HEADS 4
#define HID   64
#define OUTC  40

typedef unsigned long long u64;

// packed fp32x2 helpers (Blackwell fma.rn.f32x2 — ptxas never emits this itself)
__device__ __forceinline__ u64 pack2(float lo, float hi) {
    u64 r; asm("mov.b64 %0, {%1, %2};" : "=l"(r) : "f"(lo), "f"(hi)); return r;
}
__device__ __forceinline__ u64 dup2(float v) {
    u64 r; asm("mov.b64 %0, {%1, %1};" : "=l"(r) : "f"(v)); return r;
}
__device__ __forceinline__ void unpack2(u64 v, float& lo, float& hi) {
    asm("mov.b64 {%0, %1}, %2;" : "=f"(lo), "=f"(hi) : "l"(v));
}
__device__ __forceinline__ void ffma2(u64& d, u64 a, u64 b) {
    asm("fma.rn.f32x2 %0, %1, %2, %0;" : "+l"(d) : "l"(a), "l"(b));
}

// ---------------- scratch (static device globals; no allocations) ----------
__device__ float g_h1  [(size_t)NN * 256];   // layer-1 linear output [N, H*HID]
__device__ float g_out1[(size_t)NN * 256];   // layer-1 GAT output after ELU
__device__ float g_h2  [(size_t)NN * OUTC];  // layer-2 linear output
__device__ float g_alS1[NN * HEADS];
__device__ float g_alD1[NN * HEADS];
__device__ float g_alS2[NN];
__device__ float g_alD2[NN];
__device__ int   g_deg   [NN];
__device__ int   g_rowptr[NN + 1];
__device__ int   g_cursor[NN];
__device__ int   g_csrsrc[EE + NN];

// ---------------- CSR build ------------------------------------------------
__global__ void zero_deg_kernel(int n) {
    int i = blockIdx.x * blockDim.x + threadIdx.x;
    if (i < n) g_deg[i] = 0;
}

__global__ void deg_kernel(const int* __restrict__ dstE, int E, int Etot) {
    int i = blockIdx.x * blockDim.x + threadIdx.x;
    if (i < Etot) {
        int d = (i < E) ? dstE[i] : (i - E);   // self-loop for i >= E
        atomicAdd(&g_deg[d], 1);
    }
}

// single-block exclusive scan over g_deg -> g_rowptr, g_cursor
__global__ void scan_kernel(int n) {
    __shared__ int sums[1024];
    int tid = threadIdx.x;
    int chunk = (n + 1023) / 1024;
    int start = tid * chunk;
    int end = min(start + chunk, n);
    int s = 0;
    for (int i = start; i < end; i++) s += g_deg[i];
    sums[tid] = s;
    __syncthreads();
    for (int off = 1; off < 1024; off <<= 1) {
        int v = (tid >= off) ? sums[tid - off] : 0;
        __syncthreads();
        sums[tid] += v;
        __syncthreads();
    }
    int base = (tid > 0) ? sums[tid - 1] : 0;
    for (int i = start; i < end; i++) {
        g_rowptr[i] = base;
        g_cursor[i] = base;
        base += g_deg[i];
    }
    if (tid == 1023) g_rowptr[n] = base;
}

__global__ void scatter_kernel(const int* __restrict__ srcE,
                               const int* __restrict__ dstE, int E, int Etot) {
    int i = blockIdx.x * blockDim.x + threadIdx.x;
    if (i < Etot) {
        int s, d;
        if (i < E) { s = srcE[i]; d = dstE[i]; }
        else       { s = d = i - E; }
        int p = atomicAdd(&g_cursor[d], 1);
        g_csrsrc[p] = s;
    }
}

// ---------------- GEMM1: h1 = x @ W1  (M x 256 @ 256 x 256) ----------------
// 128x128x16 tile, 8x8 per thread via packed f32x2 (8x4 packed accs).
__global__ void __launch_bounds__(256) sgemm1_kernel(const float* __restrict__ A,
                                                     const float* __restrict__ B, int M) {
    const int BM = 128, BN = 128, BK = 16;
    const int K = 256, Ncol = 256;
    const int ASTRIDE = BM + 4; // 132: keeps 16B alignment for float4 reads
    __shared__ float As[BK][ASTRIDE];
    __shared__ float Bs[BK][BN];
    int tid = threadIdx.x;
    int tx = tid & 15;
    int ty = tid >> 4;
    int rowBase = blockIdx.y * BM;
    int colBase = blockIdx.x * BN;

    u64 acc[8][4];
    u64 z = dup2(0.f);
#pragma unroll
    for (int i = 0; i < 8; i++)
#pragma unroll
        for (int j = 0; j < 4; j++) acc[i][j] = z;

    for (int kk = 0; kk < K; kk += BK) {
#pragma unroll
        for (int l = 0; l < 2; l++) {
            int f = tid + l * 256;
            // A tile: 128 rows x 16 k ; f -> row f/4, k-quad f%4
            int ar = f >> 2, ac = (f & 3) << 2;
            float4 av = make_float4(0.f, 0.f, 0.f, 0.f);
            int grow = rowBase + ar;
            if (grow < M) av = *(const float4*)(A + (size_t)grow * K + kk + ac);
            As[ac + 0][ar] = av.x;
            As[ac + 1][ar] = av.y;
            As[ac + 2][ar] = av.z;
            As[ac + 3][ar] = av.w;
            // B tile: 16 k x 128 cols
            int br = f >> 5, bc = (f & 31) << 2;
            float4 bv = *(const float4*)(B + (size_t)(kk + br) * Ncol + colBase + bc);
            *(float4*)&Bs[br][bc] = bv;
        }
        __syncthreads();
#pragma unroll
        for (int k = 0; k < BK; k++) {
            float a_frag[8];
            *(float4*)&a_frag[0] = *(const float4*)&As[k][ty * 8];
            *(float4*)&a_frag[4] = *(const float4*)&As[k][ty * 8 + 4];
            u64 adup[8];
#pragma unroll
            for (int i = 0; i < 8; i++) adup[i] = dup2(a_frag[i]);
            u64 bp[4];
#pragma unroll
            for (int p = 0; p < 4; p++)
                bp[p] = *(const u64*)&Bs[k][tx * 8 + 2 * p];
#pragma unroll
            for (int i = 0; i < 8; i++)
#pragma unroll
                for (int p = 0; p < 4; p++) ffma2(acc[i][p], adup[i], bp[p]);
        }
        __syncthreads();
    }
#pragma unroll
    for (int i = 0; i < 8; i++) {
        int grow = rowBase + ty * 8 + i;
        if (grow >= M) continue;
#pragma unroll
        for (int p = 0; p < 4; p++)
            *(u64*)(g_h1 + (size_t)grow * Ncol + colBase + tx * 8 + 2 * p) = acc[i][p];
    }
}

// ---------------- per-node attention logits, layer 1 -----------------------
__global__ void al1_kernel(const float* __restrict__ a_src,
                           const float* __restrict__ a_dst, int N) {
    int i = blockIdx.x * blockDim.x + threadIdx.x;
    if (i >= N * HEADS) return;
    int n = i >> 2, h = i & 3;
    const float4* hp = (const float4*)(g_h1 + (size_t)n * 256 + h * HID);
    const float4* sp = (const float4*)(a_src + h * HID);
    const float4* dp = (const float4*)(a_dst + h * HID);
    float s = 0.f, d = 0.f;
#pragma unroll
    for (int q = 0; q < HID / 4; q++) {
        float4 hv = hp[q], sv = sp[q], dv = dp[q];
        s += hv.x * sv.x + hv.y * sv.y + hv.z * sv.z + hv.w * sv.w;
        d += hv.x * dv.x + hv.y * dv.y + hv.z * dv.z + hv.w * dv.w;
    }
    g_alS1[i] = s;
    g_alD1[i] = d;
}

// ---------------- fused softmax + aggregation, layer 1 ---------------------
// one warp per (node, head); lane covers channels {2*lane, 2*lane+1} packed
__global__ void __launch_bounds__(256) agg1_kernel(const float* __restrict__ b1, int N) {
    int gw = blockIdx.x * 8 + (threadIdx.x >> 5);
    int lane = threadIdx.x & 31;
    if (gw >= N * HEADS) return;
    int n = gw >> 2, hh = gw & 3;
    int start = g_rowptr[n], end = g_rowptr[n + 1];
    float ad = g_alD1[n * HEADS + hh];

    // pass 1: segment max over lrelu(alS[src] + alD[dst])
    float m = -INFINITY;
    for (int j = start + lane; j < end; j += 32) {
        int s = g_csrsrc[j];
        float v = g_alS1[s * HEADS + hh] + ad;
        v = (v > 0.f) ? v : 0.2f * v;
        m = fmaxf(m, v);
    }
#pragma unroll
    for (int o = 16; o; o >>= 1) m = fmaxf(m, __shfl_xor_sync(0xffffffffu, m, o));

    // pass 2: exp weights staged in smem (computed once per edge), then
    // all lanes accumulate their packed channel pair over the chunk.
    __shared__ float sw_w[8][32];
    __shared__ int   sw_s[8][32];
    int w = threadIdx.x >> 5;
    u64 acc = dup2(0.f);
    float ssum = 0.f;
    for (int base = start; base < end; base += 32) {
        int cnt = min(32, end - base);
        float wv = 0.f;
        if (lane < cnt) {
            int s = g_csrsrc[base + lane];
            float v = g_alS1[s * HEADS + hh] + ad;
            v = (v > 0.f) ? v : 0.2f * v;
            wv = __expf(v - m);
            sw_w[w][lane] = wv;
            sw_s[w][lane] = s;
        }
        ssum += wv;
        __syncwarp();
        for (int j = 0; j < cnt; j++) {
            u64 a = dup2(sw_w[w][j]);
            const float* hp = g_h1 + (size_t)sw_s[w][j] * 256 + hh * HID;
            u64 hv = *(const u64*)(hp + 2 * lane);
            ffma2(acc, a, hv);
        }
        __syncwarp();
    }
#pragma unroll
    for (int o = 16; o; o >>= 1) ssum += __shfl_xor_sync(0xffffffffu, ssum, o);
    float inv = 1.0f / (ssum + 1e-16f);
    float r0, r1;
    unpack2(acc, r0, r1);
    float2 bv = *(const float2*)(b1 + hh * HID + 2 * lane);
    r0 = r0 * inv + bv.x;
    r1 = r1 * inv + bv.y;
    // ELU
    r0 = (r0 > 0.f) ? r0 : expm1f(r0);
    r1 = (r1 > 0.f) ? r1 : expm1f(r1);
    *(float2*)(g_out1 + (size_t)n * 256 + hh * HID + 2 * lane) = make_float2(r0, r1);
}

// ---------------- GEMM2: h2 = out1 @ W2  (M x 256 @ 256 x 40) --------------
// W2 cached fully in smem; 32 rows per block; thread computes 5 outputs.
__global__ void __launch_bounds__(256) gemm2_kernel(const float* __restrict__ W, int M) {
    __shared__ float Ws[256 * OUTC];  // 40 KB
    int tid = threadIdx.x;
    for (int i = tid; i < (256 * OUTC) / 4; i += 256)
        *(float4*)&Ws[i * 4] = *(const float4*)(W + i * 4);
    __syncthreads();

    int r = tid >> 3;          // 0..31  local row
    int g = tid & 7;           // 0..7   col group (5 cols each)
    int grow = blockIdx.x * 32 + r;
    if (grow >= M) return;

    float acc[5] = {0.f, 0.f, 0.f, 0.f, 0.f};
    const float4* ap = (const float4*)(g_out1 + (size_t)grow * 256);
#pragma unroll 4
    for (int k4 = 0; k4 < 64; k4++) {
        float4 a4 = __ldg(&ap[k4]);
        float av[4] = {a4.x, a4.y, a4.z, a4.w};
#pragma unroll
        for (int q = 0; q < 4; q++) {
            const float* wrow = &Ws[(k4 * 4 + q) * OUTC + g * 5];
#pragma unroll
            for (int j = 0; j < 5; j++) acc[j] += av[q] * wrow[j];
        }
    }
#pragma unroll
    for (int j = 0; j < 5; j++) g_h2[(size_t)grow * OUTC + g * 5 + j] = acc[j];
}

// ---------------- per-node attention logits, layer 2 -----------------------
__global__ void al2_kernel(const float* __restrict__ a_src,
                           const float* __restrict__ a_dst, int N) {
    int n = blockIdx.x * blockDim.x + threadIdx.x;
    if (n >= N) return;
    const float4* hp = (const float4*)(g_h2 + (size_t)n * OUTC);
    const float4* sp = (const float4*)a_src;
    const float4* dp = (const float4*)a_dst;
    float s = 0.f, d = 0.f;
#pragma unroll
    for (int q = 0; q < OUTC / 4; q++) {
        float4 hv = hp[q], sv = sp[q], dv = dp[q];
        s += hv.x * sv.x + hv.y * sv.y + hv.z * sv.z + hv.w * sv.w;
        d += hv.x * dv.x + hv.y * dv.y + hv.z * dv.z + hv.w * dv.w;
    }
    g_alS2[n] = s;
    g_alD2[n] = d;
}

// ---------------- fused softmax + aggregation, layer 2 ---------------------
// one warp per node; lanes 0..19 cover channels {2*lane, 2*lane+1} packed
__global__ void __launch_bounds__(256) agg2_kernel(const float* __restrict__ b2,
                                                   float* __restrict__ out, int N) {
    int n = blockIdx.x * 8 + (threadIdx.x >> 5);
    int lane = threadIdx.x & 31;
    if (n >= N) return;
    int start = g_rowptr[n], end = g_rowptr[n + 1];
    float ad = g_alD2[n];

    float m = -INFINITY;
    for (int j = start + lane; j < end; j += 32) {
        int s = g_csrsrc[j];
        float v = g_alS2[s] + ad;
        v = (v > 0.f) ? v : 0.2f * v;
        m = fmaxf(m, v);
    }
#pragma unroll
    for (int o = 16; o; o >>= 1) m = fmaxf(m, __shfl_xor_sync(0xffffffffu, m, o));

    __shared__ float sw_w[8][32];
    __shared__ int   sw_s[8][32];
    int w = threadIdx.x >> 5;
    u64 acc = dup2(0.f);
    float ssum = 0.f;
    for (int base = start; base < end; base += 32) {
        int cnt = min(32, end - base);
        float wv = 0.f;
        if (lane < cnt) {
            int s = g_csrsrc[base + lane];
            float v = g_alS2[s] + ad;
            v = (v > 0.f) ? v : 0.2f * v;
            wv = __expf(v - m);
            sw_w[w][lane] = wv;
            sw_s[w][lane] = s;
        }
        ssum += wv;
        __syncwarp();
        if (lane < OUTC / 2) {
            for (int j = 0; j < cnt; j++) {
                u64 a = dup2(sw_w[w][j]);
                const float* hp = g_h2 + (size_t)sw_s[w][j] * OUTC;
                u64 hv = *(const u64*)(hp + 2 * lane);
                ffma2(acc, a, hv);
            }
        }
        __syncwarp();
    }
#pragma unroll
    for (int o = 16; o; o >>= 1) ssum += __shfl_xor_sync(0xffffffffu, ssum, o);
    float inv = 1.0f / (ssum + 1e-16f);
    if (lane < OUTC / 2) {
        float r0, r1;
        unpack2(acc, r0, r1);
        float2 bv = *(const float2*)(b2 + 2 * lane);
        *(float2*)(out + (size_t)n * OUTC + 2 * lane) =
            make_float2(r0 * inv + bv.x, r1 * inv + bv.y);
    }
}

// ---------------- launch ----------------------------------------------------
extern "C" void kernel_launch(void* const* d_in, const int* in_sizes, int n_in,
                              void* d_out, int out_size) {
    const float* x      = (const float*)d_in[0];
    const int*   ei     = (const int*)d_in[1];
    const float* W1     = (const float*)d_in[2];
    const float* a_src1 = (const float*)d_in[3];
    const float* a_dst1 = (const float*)d_in[4];
    const float* b1     = (const float*)d_in[5];
    const float* W2     = (const float*)d_in[6];
    const float* a_src2 = (const float*)d_in[7];
    const float* a_dst2 = (const float*)d_in[8];
    const float* b2     = (const float*)d_in[9];
    float* out = (float*)d_out;

    int N = in_sizes[0] / 256;   // 50000
    int E = in_sizes[1] / 2;     // 800000
    int Etot = E + N;
    const int* srcE = ei;
    const int* dstE = ei + E;

    // CSR build (by destination, self-loops appended)
    zero_deg_kernel<<<(N + 255) / 256, 256>>>(N);
    deg_kernel<<<(Etot + 255) / 256, 256>>>(dstE, E, Etot);
    scan_kernel<<<1, 1024>>>(N);
    scatter_kernel<<<(Etot + 255) / 256, 256>>>(srcE, dstE, E, Etot);

    // layer 1
    sgemm1_kernel<<<dim3(2, (N + 127) / 128), 256>>>(x, W1, N);
    al1_kernel<<<(N * HEADS + 255) / 256, 256>>>(a_src1, a_dst1, N);
    agg1_kernel<<<(N * HEADS + 7) / 8, 256>>>(b1, N);

    // layer 2
    gemm2_kernel<<<(N + 31) / 32, 256>>>(W2, N);
    al2_kernel<<<(N + 255) / 256, 256>>>(a_src2, a_dst2, N);
    agg2_kernel<<<(N + 7) / 8, 256>>>(b2, out, N);
}

// round 7
// speedup vs baseline: 1.2074x; 1.2074x over previous
#include <cuda_runtime.h>
#include <cuda_bf16.h>
#include <math.h>
#include <stdint.h>

#define NN    50000
#define MPAD  50048        // 391 * 128
#define EE    800000
#define HEADS 4
#define HID   64
#define OUTC  40

// ---------------- scratch (static device globals; no allocations) ----------
__device__ float g_h1  [(size_t)MPAD * 256];  // layer-1 linear output [N, H*HID]
__device__ float g_out1[(size_t)NN * 256];    // layer-1 GAT output after ELU
__device__ float g_h2  [(size_t)NN * OUTC];   // layer-2 linear output
__device__ float g_alS1[NN * HEADS];
__device__ float g_alD1[NN * HEADS];
__device__ float g_alS2[NN];
__device__ float g_alD2[NN];
__device__ int   g_deg   [NN];
__device__ int   g_rowptr[NN + 1];
__device__ int   g_cursor[NN];
__device__ int   g_csrsrc[EE + NN];
// bf16x3 split operands for tensor-core GEMM1
__device__ __nv_bfloat16 g_xhi[(size_t)MPAD * 256];
__device__ __nv_bfloat16 g_xlo[(size_t)MPAD * 256];
__device__ __nv_bfloat16 g_bhi[256 * 256];   // W1^T  [N=256][K=256]
__device__ __nv_bfloat16 g_blo[256 * 256];

// ---------------- PTX helpers (portable sm_80+ instructions only) ----------
__device__ __forceinline__ uint32_t smem_u32(const void* p) {
    uint32_t a;
    asm("{ .reg .u64 t; cvta.to.shared.u64 t, %1; cvt.u32.u64 %0, t; }" : "=r"(a) : "l"(p));
    return a;
}
__device__ __forceinline__ void ldsm4(uint32_t* r, uint32_t addr) {
    asm volatile("ldmatrix.sync.aligned.m8n8.x4.shared.b16 {%0,%1,%2,%3}, [%4];"
                 : "=r"(r[0]), "=r"(r[1]), "=r"(r[2]), "=r"(r[3]) : "r"(addr));
}
__device__ __forceinline__ void mma_bf16(float* c, const uint32_t* a, const uint32_t* b) {
    asm volatile(
        "mma.sync.aligned.m16n8k16.row.col.f32.bf16.bf16.f32 "
        "{%0,%1,%2,%3}, {%4,%5,%6,%7}, {%8,%9}, {%0,%1,%2,%3};"
        : "+f"(c[0]), "+f"(c[1]), "+f"(c[2]), "+f"(c[3])
        : "r"(a[0]), "r"(a[1]), "r"(a[2]), "r"(a[3]), "r"(b[0]), "r"(b[1]));
}

// ---------------- CSR build ------------------------------------------------
__global__ void zero_deg_kernel(int n) {
    int i = blockIdx.x * blockDim.x + threadIdx.x;
    if (i < n) g_deg[i] = 0;
}

__global__ void deg_kernel(const int* __restrict__ dstE, int E, int Etot) {
    int i = blockIdx.x * blockDim.x + threadIdx.x;
    if (i < Etot) {
        int d = (i < E) ? dstE[i] : (i - E);   // self-loop for i >= E
        atomicAdd(&g_deg[d], 1);
    }
}

__global__ void scan_kernel(int n) {
    __shared__ int sums[1024];
    int tid = threadIdx.x;
    int chunk = (n + 1023) / 1024;
    int start = tid * chunk;
    int end = min(start + chunk, n);
    int s = 0;
    for (int i = start; i < end; i++) s += g_deg[i];
    sums[tid] = s;
    __syncthreads();
    for (int off = 1; off < 1024; off <<= 1) {
        int v = (tid >= off) ? sums[tid - off] : 0;
        __syncthreads();
        sums[tid] += v;
        __syncthreads();
    }
    int base = (tid > 0) ? sums[tid - 1] : 0;
    for (int i = start; i < end; i++) {
        g_rowptr[i] = base;
        g_cursor[i] = base;
        base += g_deg[i];
    }
    if (tid == 1023) g_rowptr[n] = base;
}

__global__ void scatter_kernel(const int* __restrict__ srcE,
                               const int* __restrict__ dstE, int E, int Etot) {
    int i = blockIdx.x * blockDim.x + threadIdx.x;
    if (i < Etot) {
        int s, d;
        if (i < E) { s = srcE[i]; d = dstE[i]; }
        else       { s = d = i - E; }
        int p = atomicAdd(&g_cursor[d], 1);
        g_csrsrc[p] = s;
    }
}

// ---------------- bf16 hi/lo split of x (padded to MPAD rows) ---------------
__global__ void convx_kernel(const float* __restrict__ x, int M) {
    int i = blockIdx.x * blockDim.x + threadIdx.x;   // one float4 per thread
    if (i >= MPAD * 64) return;
    int row = i >> 6;
    float4 v = make_float4(0.f, 0.f, 0.f, 0.f);
    if (row < M) v = *(const float4*)(x + (size_t)i * 4);
    __nv_bfloat16 h0 = __float2bfloat16(v.x);
    __nv_bfloat16 h1 = __float2bfloat16(v.y);
    __nv_bfloat16 h2 = __float2bfloat16(v.z);
    __nv_bfloat16 h3 = __float2bfloat16(v.w);
    __nv_bfloat162 a; a.x = h0; a.y = h1;
    __nv_bfloat162 b; b.x = h2; b.y = h3;
    *(__nv_bfloat162*)(g_xhi + (size_t)i * 4)     = a;
    *(__nv_bfloat162*)(g_xhi + (size_t)i * 4 + 2) = b;
    __nv_bfloat162 la, lb;
    la.x = __float2bfloat16(v.x - __bfloat162float(h0));
    la.y = __float2bfloat16(v.y - __bfloat162float(h1));
    lb.x = __float2bfloat16(v.z - __bfloat162float(h2));
    lb.y = __float2bfloat16(v.w - __bfloat162float(h3));
    *(__nv_bfloat162*)(g_xlo + (size_t)i * 4)     = la;
    *(__nv_bfloat162*)(g_xlo + (size_t)i * 4 + 2) = lb;
}

// ---------------- W1 transpose + split: g_b* = W1^T [n][k] ------------------
__global__ void convw_kernel(const float* __restrict__ W) {
    int i = blockIdx.x * blockDim.x + threadIdx.x;
    if (i >= 256 * 256) return;
    int n = i >> 8, k = i & 255;
    float v = W[k * 256 + n];
    __nv_bfloat16 h = __float2bfloat16(v);
    g_bhi[i] = h;
    g_blo[i] = __float2bfloat16(v - __bfloat162float(h));
}

// ---------------- GEMM1 via mma.sync bf16x3 ---------------------------------
// CTA = 128x128 output tile; 8 warps as 4(m) x 2(n); warp = 32x64.
// K=256 in 8 chunks of 32. Effective 3 passes: Ah*Bh + Ah*Bl + Al*Bh.
// smem rows padded to 40 bf16 (80B): granule index (5r+c) mod 8 covers all
// eight 16B banks -> conflict-free ldmatrix without swizzle.
#define SROW 40
__global__ void __launch_bounds__(256, 1) mma1_kernel() {
    __shared__ __align__(16) __nv_bfloat16 sAhi[128 * SROW];
    __shared__ __align__(16) __nv_bfloat16 sAlo[128 * SROW];
    __shared__ __align__(16) __nv_bfloat16 sBhi[128 * SROW];
    __shared__ __align__(16) __nv_bfloat16 sBlo[128 * SROW];

    int tid = threadIdx.x;
    int lane = tid & 31, wid = tid >> 5;
    int warp_m = (wid & 3) * 32;
    int warp_n = (wid >> 2) * 64;
    int rowBase = blockIdx.y * 128;
    int colBase = blockIdx.x * 128;

    uint32_t aHiB = smem_u32(sAhi), aLoB = smem_u32(sAlo);
    uint32_t bHiB = smem_u32(sBhi), bLoB = smem_u32(sBlo);

    float acc[2][8][4];
#pragma unroll
    for (int im = 0; im < 2; im++)
#pragma unroll
        for (int jn = 0; jn < 8; jn++)
#pragma unroll
            for (int q = 0; q < 4; q++) acc[im][jn][q] = 0.f;

    uint4 pAh[2], pAl[2], pBh[2], pBl[2];
    // prefetch chunk 0
#pragma unroll
    for (int l = 0; l < 2; l++) {
        int v = tid + (l << 8);
        int r = v >> 2, cg = v & 3;
        size_t ga = (size_t)(rowBase + r) * 256 + cg * 8;
        size_t gb = (size_t)(colBase + r) * 256 + cg * 8;
        pAh[l] = *(const uint4*)(g_xhi + ga);
        pAl[l] = *(const uint4*)(g_xlo + ga);
        pBh[l] = *(const uint4*)(g_bhi + gb);
        pBl[l] = *(const uint4*)(g_blo + gb);
    }

    for (int c = 0; c < 8; c++) {
        __syncthreads();   // previous chunk's compute done before smem overwrite
#pragma unroll
        for (int l = 0; l < 2; l++) {
            int v = tid + (l << 8);
            int r = v >> 2, cg = v & 3;
            int so = r * SROW + cg * 8;
            *(uint4*)(sAhi + so) = pAh[l];
            *(uint4*)(sAlo + so) = pAl[l];
            *(uint4*)(sBhi + so) = pBh[l];
            *(uint4*)(sBlo + so) = pBl[l];
        }
        __syncthreads();
        if (c < 7) {
            int kk = (c + 1) * 32;
#pragma unroll
            for (int l = 0; l < 2; l++) {
                int v = tid + (l << 8);
                int r = v >> 2, cg = v & 3;
                size_t ga = (size_t)(rowBase + r) * 256 + kk + cg * 8;
                size_t gb = (size_t)(colBase + r) * 256 + kk + cg * 8;
                pAh[l] = *(const uint4*)(g_xhi + ga);
                pAl[l] = *(const uint4*)(g_xlo + ga);
                pBh[l] = *(const uint4*)(g_bhi + gb);
                pBl[l] = *(const uint4*)(g_blo + gb);
            }
        }
#pragma unroll
        for (int ks = 0; ks < 2; ks++) {
            uint32_t fAh[2][4], fAl[2][4];
#pragma unroll
            for (int im = 0; im < 2; im++) {
                uint32_t off = ((warp_m + im * 16 + (lane & 15)) * SROW +
                                ks * 16 + (lane >> 4) * 8) * 2;
                ldsm4(fAh[im], aHiB + off);
                ldsm4(fAl[im], aLoB + off);
            }
            uint32_t fBh[8][2], fBl[8][2];
#pragma unroll
            for (int j2 = 0; j2 < 4; j2++) {
                int s = lane >> 3;
                uint32_t off = ((warp_n + j2 * 16 + ((s >> 1) << 3) + (lane & 7)) * SROW +
                                ks * 16 + ((s & 1) << 3)) * 2;
                uint32_t t[4];
                ldsm4(t, bHiB + off);
                fBh[j2 * 2][0] = t[0]; fBh[j2 * 2][1] = t[1];
                fBh[j2 * 2 + 1][0] = t[2]; fBh[j2 * 2 + 1][1] = t[3];
                ldsm4(t, bLoB + off);
                fBl[j2 * 2][0] = t[0]; fBl[j2 * 2][1] = t[1];
                fBl[j2 * 2 + 1][0] = t[2]; fBl[j2 * 2 + 1][1] = t[3];
            }
#pragma unroll
            for (int im = 0; im < 2; im++)
#pragma unroll
                for (int jn = 0; jn < 8; jn++) mma_bf16(acc[im][jn], fAh[im], fBh[jn]);
#pragma unroll
            for (int im = 0; im < 2; im++)
#pragma unroll
                for (int jn = 0; jn < 8; jn++) mma_bf16(acc[im][jn], fAh[im], fBl[jn]);
#pragma unroll
            for (int im = 0; im < 2; im++)
#pragma unroll
                for (int jn = 0; jn < 8; jn++) mma_bf16(acc[im][jn], fAl[im], fBh[jn]);
        }
    }

    // epilogue: direct stores (g_h1 has MPAD rows, no bound check needed)
#pragma unroll
    for (int im = 0; im < 2; im++) {
        int row0 = rowBase + warp_m + im * 16 + (lane >> 2);
#pragma unroll
        for (int jn = 0; jn < 8; jn++) {
            int col = colBase + warp_n + jn * 8 + (lane & 3) * 2;
            *(float2*)(g_h1 + (size_t)row0 * 256 + col) =
                make_float2(acc[im][jn][0], acc[im][jn][1]);
            *(float2*)(g_h1 + (size_t)(row0 + 8) * 256 + col) =
                make_float2(acc[im][jn][2], acc[im][jn][3]);
        }
    }
}

// ---------------- per-node attention logits, layer 1 -----------------------
__global__ void al1_kernel(const float* __restrict__ a_src,
                           const float* __restrict__ a_dst, int N) {
    int i = blockIdx.x * blockDim.x + threadIdx.x;
    if (i >= N * HEADS) return;
    int n = i >> 2, h = i & 3;
    const float4* hp = (const float4*)(g_h1 + (size_t)n * 256 + h * HID);
    const float4* sp = (const float4*)(a_src + h * HID);
    const float4* dp = (const float4*)(a_dst + h * HID);
    float s = 0.f, d = 0.f;
#pragma unroll
    for (int q = 0; q < HID / 4; q++) {
        float4 hv = hp[q], sv = sp[q], dv = dp[q];
        s += hv.x * sv.x + hv.y * sv.y + hv.z * sv.z + hv.w * sv.w;
        d += hv.x * dv.x + hv.y * dv.y + hv.z * dv.z + hv.w * dv.w;
    }
    g_alS1[i] = s;
    g_alD1[i] = d;
}

// ---------------- fused softmax + aggregation, layer 1 ---------------------
__global__ void __launch_bounds__(256) agg1_kernel(const float* __restrict__ b1, int N) {
    int gw = blockIdx.x * 8 + (threadIdx.x >> 5);
    int lane = threadIdx.x & 31;
    if (gw >= N * HEADS) return;
    int n = gw >> 2, hh = gw & 3;
    int start = g_rowptr[n], end = g_rowptr[n + 1];
    float ad = g_alD1[n * HEADS + hh];

    float m = -INFINITY;
    for (int j = start + lane; j < end; j += 32) {
        int s = g_csrsrc[j];
        float v = g_alS1[s * HEADS + hh] + ad;
        v = (v > 0.f) ? v : 0.2f * v;
        m = fmaxf(m, v);
    }
#pragma unroll
    for (int o = 16; o; o >>= 1) m = fmaxf(m, __shfl_xor_sync(0xffffffffu, m, o));

    __shared__ float sw_w[8][32];
    __shared__ int   sw_s[8][32];
    int w = threadIdx.x >> 5;
    float acc0 = 0.f, acc1 = 0.f, ssum = 0.f;
    for (int base = start; base < end; base += 32) {
        int cnt = min(32, end - base);
        float wv = 0.f;
        if (lane < cnt) {
            int s = g_csrsrc[base + lane];
            float v = g_alS1[s * HEADS + hh] + ad;
            v = (v > 0.f) ? v : 0.2f * v;
            wv = __expf(v - m);
            sw_w[w][lane] = wv;
            sw_s[w][lane] = s;
        }
        ssum += wv;
        __syncwarp();
        for (int j = 0; j < cnt; j++) {
            float a = sw_w[w][j];
            const float* hp = g_h1 + (size_t)sw_s[w][j] * 256 + hh * HID;
            acc0 += a * hp[lane];
            acc1 += a * hp[lane + 32];
        }
        __syncwarp();
    }
#pragma unroll
    for (int o = 16; o; o >>= 1) ssum += __shfl_xor_sync(0xffffffffu, ssum, o);
    float inv = 1.0f / (ssum + 1e-16f);
    float r0 = acc0 * inv + b1[hh * HID + lane];
    float r1 = acc1 * inv + b1[hh * HID + lane + 32];
    r0 = (r0 > 0.f) ? r0 : expm1f(r0);
    r1 = (r1 > 0.f) ? r1 : expm1f(r1);
    size_t o0 = (size_t)n * 256 + hh * HID;
    g_out1[o0 + lane]      = r0;
    g_out1[o0 + lane + 32] = r1;
}

// ---------------- GEMM2: h2 = out1 @ W2  (M x 256 @ 256 x 40) --------------
__global__ void __launch_bounds__(256) gemm2_kernel(const float* __restrict__ W, int M) {
    __shared__ float Ws[256 * OUTC];  // 40 KB
    int tid = threadIdx.x;
    for (int i = tid; i < (256 * OUTC) / 4; i += 256)
        *(float4*)&Ws[i * 4] = *(const float4*)(W + i * 4);
    __syncthreads();

    int r = tid >> 3;
    int g = tid & 7;
    int grow = blockIdx.x * 32 + r;
    if (grow >= M) return;

    float acc[5] = {0.f, 0.f, 0.f, 0.f, 0.f};
    const float4* ap = (const float4*)(g_out1 + (size_t)grow * 256);
#pragma unroll 4
    for (int k4 = 0; k4 < 64; k4++) {
        float4 a4 = __ldg(&ap[k4]);
        float av[4] = {a4.x, a4.y, a4.z, a4.w};
#pragma unroll
        for (int q = 0; q < 4; q++) {
            const float* wrow = &Ws[(k4 * 4 + q) * OUTC + g * 5];
#pragma unroll
            for (int j = 0; j < 5; j++) acc[j] += av[q] * wrow[j];
        }
    }
#pragma unroll
    for (int j = 0; j < 5; j++) g_h2[(size_t)grow * OUTC + g * 5 + j] = acc[j];
}

// ---------------- per-node attention logits, layer 2 -----------------------
__global__ void al2_kernel(const float* __restrict__ a_src,
                           const float* __restrict__ a_dst, int N) {
    int n = blockIdx.x * blockDim.x + threadIdx.x;
    if (n >= N) return;
    const float4* hp = (const float4*)(g_h2 + (size_t)n * OUTC);
    const float4* sp = (const float4*)a_src;
    const float4* dp = (const float4*)a_dst;
    float s = 0.f, d = 0.f;
#pragma unroll
    for (int q = 0; q < OUTC / 4; q++) {
        float4 hv = hp[q], sv = sp[q], dv = dp[q];
        s += hv.x * sv.x + hv.y * sv.y + hv.z * sv.z + hv.w * sv.w;
        d += hv.x * dv.x + hv.y * dv.y + hv.z * dv.z + hv.w * dv.w;
    }
    g_alS2[n] = s;
    g_alD2[n] = d;
}

// ---------------- fused softmax + aggregation, layer 2 ---------------------
__global__ void __launch_bounds__(256) agg2_kernel(const float* __restrict__ b2,
                                                   float* __restrict__ out, int N) {
    int n = blockIdx.x * 8 + (threadIdx.x >> 5);
    int lane = threadIdx.x & 31;
    if (n >= N) return;
    int start = g_rowptr[n], end = g_rowptr[n + 1];
    float ad = g_alD2[n];

    float m = -INFINITY;
    for (int j = start + lane; j < end; j += 32) {
        int s = g_csrsrc[j];
        float v = g_alS2[s] + ad;
        v = (v > 0.f) ? v : 0.2f * v;
        m = fmaxf(m, v);
    }
#pragma unroll
    for (int o = 16; o; o >>= 1) m = fmaxf(m, __shfl_xor_sync(0xffffffffu, m, o));

    __shared__ float sw_w[8][32];
    __shared__ int   sw_s[8][32];
    int w = threadIdx.x >> 5;
    float acc0 = 0.f, acc1 = 0.f, ssum = 0.f;
    for (int base = start; base < end; base += 32) {
        int cnt = min(32, end - base);
        float wv = 0.f;
        if (lane < cnt) {
            int s = g_csrsrc[base + lane];
            float v = g_alS2[s] + ad;
            v = (v > 0.f) ? v : 0.2f * v;
            wv = __expf(v - m);
            sw_w[w][lane] = wv;
            sw_s[w][lane] = s;
        }
        ssum += wv;
        __syncwarp();
        for (int j = 0; j < cnt; j++) {
            float a = sw_w[w][j];
            const float* hp = g_h2 + (size_t)sw_s[w][j] * OUTC;
            acc0 += a * hp[lane];
            if (lane < OUTC - 32) acc1 += a * hp[lane + 32];
        }
        __syncwarp();
    }
#pragma unroll
    for (int o = 16; o; o >>= 1) ssum += __shfl_xor_sync(0xffffffffu, ssum, o);
    float inv = 1.0f / (ssum + 1e-16f);
    out[(size_t)n * OUTC + lane] = acc0 * inv + b2[lane];
    if (lane < OUTC - 32)
        out[(size_t)n * OUTC + lane + 32] = acc1 * inv + b2[lane + 32];
}

// ---------------- launch ----------------------------------------------------
extern "C" void kernel_launch(void* const* d_in, const int* in_sizes, int n_in,
                              void* d_out, int out_size) {
    const float* x      = (const float*)d_in[0];
    const int*   ei     = (const int*)d_in[1];
    const float* W1     = (const float*)d_in[2];
    const float* a_src1 = (const float*)d_in[3];
    const float* a_dst1 = (const float*)d_in[4];
    const float* b1     = (const float*)d_in[5];
    const float* W2     = (const float*)d_in[6];
    const float* a_src2 = (const float*)d_in[7];
    const float* a_dst2 = (const float*)d_in[8];
    const float* b2     = (const float*)d_in[9];
    float* out = (float*)d_out;

    int N = in_sizes[0] / 256;   // 50000
    int E = in_sizes[1] / 2;     // 800000
    int Etot = E + N;
    const int* srcE = ei;
    const int* dstE = ei + E;

    // CSR build (by destination, self-loops appended)
    zero_deg_kernel<<<(N + 255) / 256, 256>>>(N);
    deg_kernel<<<(Etot + 255) / 256, 256>>>(dstE, E, Etot);
    scan_kernel<<<1, 1024>>>(N);
    scatter_kernel<<<(Etot + 255) / 256, 256>>>(srcE, dstE, E, Etot);

    // layer 1: bf16x3 split + mma.sync tensor-core GEMM
    convx_kernel<<<(MPAD * 64 + 255) / 256, 256>>>(x, N);
    convw_kernel<<<(256 * 256 + 255) / 256, 256>>>(W1);
    mma1_kernel<<<dim3(2, MPAD / 128), 256>>>();
    al1_kernel<<<(N * HEADS + 255) / 256, 256>>>(a_src1, a_dst1, N);
    agg1_kernel<<<(N * HEADS + 7) / 8, 256>>>(b1, N);

    // layer 2
    gemm2_kernel<<<(N + 31) / 32, 256>>>(W2, N);
    al2_kernel<<<(N + 255) / 256, 256>>>(a_src2, a_dst2, N);
    agg2_kernel<<<(N + 7) / 8, 256>>>(b2, out, N);
}

// round 8
// speedup vs baseline: 1.5740x; 1.3036x over previous
#include <cuda_runtime.h>
#include <cuda_bf16.h>
#include <math.h>
#include <stdint.h>

#define NN    50000
#define MPAD  50048        // 391 * 128
#define EE    800000
#define HEADS 4
#define HID   64
#define OUTC  40

// ---------------- scratch (static device globals; no allocations) ----------
__device__ float g_h1  [(size_t)MPAD * 256];  // layer-1 linear output [N, H*HID]
__device__ float g_out1[(size_t)NN * 256];    // layer-1 GAT output after ELU
__device__ float g_h2  [(size_t)NN * OUTC];   // layer-2 linear output
__device__ float g_alS1[NN * HEADS];
__device__ float g_alD1[NN * HEADS];
__device__ float g_alS2[NN];
__device__ float g_alD2[NN];
__device__ int   g_deg   [NN];
__device__ int   g_rowptr[NN + 1];
__device__ int   g_cursor[NN];
__device__ int   g_csrsrc[EE + NN];
// bf16x3 split operands for tensor-core GEMM1
__device__ __nv_bfloat16 g_xhi[(size_t)MPAD * 256];
__device__ __nv_bfloat16 g_xlo[(size_t)MPAD * 256];
__device__ __nv_bfloat16 g_bhi[256 * 256];   // W1^T  [N=256][K=256]
__device__ __nv_bfloat16 g_blo[256 * 256];

// ---------------- PTX helpers (portable sm_80+ instructions only) ----------
__device__ __forceinline__ uint32_t smem_u32(const void* p) {
    uint32_t a;
    asm("{ .reg .u64 t; cvta.to.shared.u64 t, %1; cvt.u32.u64 %0, t; }" : "=r"(a) : "l"(p));
    return a;
}
__device__ __forceinline__ void ldsm4(uint32_t* r, uint32_t addr) {
    asm volatile("ldmatrix.sync.aligned.m8n8.x4.shared.b16 {%0,%1,%2,%3}, [%4];"
                 : "=r"(r[0]), "=r"(r[1]), "=r"(r[2]), "=r"(r[3]) : "r"(addr));
}
__device__ __forceinline__ void mma_bf16(float* c, const uint32_t* a, const uint32_t* b) {
    asm volatile(
        "mma.sync.aligned.m16n8k16.row.col.f32.bf16.bf16.f32 "
        "{%0,%1,%2,%3}, {%4,%5,%6,%7}, {%8,%9}, {%0,%1,%2,%3};"
        : "+f"(c[0]), "+f"(c[1]), "+f"(c[2]), "+f"(c[3])
        : "r"(a[0]), "r"(a[1]), "r"(a[2]), "r"(a[3]), "r"(b[0]), "r"(b[1]));
}

// ---------------- CSR build ------------------------------------------------
__global__ void zero_deg_kernel(int n) {
    int i = blockIdx.x * blockDim.x + threadIdx.x;
    if (i < n) g_deg[i] = 0;
}

__global__ void deg_kernel(const int* __restrict__ dstE, int E, int Etot) {
    int i = blockIdx.x * blockDim.x + threadIdx.x;
    if (i < Etot) {
        int d = (i < E) ? dstE[i] : (i - E);   // self-loop for i >= E
        atomicAdd(&g_deg[d], 1);
    }
}

__global__ void scan_kernel(int n) {
    __shared__ int sums[1024];
    int tid = threadIdx.x;
    int chunk = (n + 1023) / 1024;
    int start = tid * chunk;
    int end = min(start + chunk, n);
    int s = 0;
    for (int i = start; i < end; i++) s += g_deg[i];
    sums[tid] = s;
    __syncthreads();
    for (int off = 1; off < 1024; off <<= 1) {
        int v = (tid >= off) ? sums[tid - off] : 0;
        __syncthreads();
        sums[tid] += v;
        __syncthreads();
    }
    int base = (tid > 0) ? sums[tid - 1] : 0;
    for (int i = start; i < end; i++) {
        g_rowptr[i] = base;
        g_cursor[i] = base;
        base += g_deg[i];
    }
    if (tid == 1023) g_rowptr[n] = base;
}

__global__ void scatter_kernel(const int* __restrict__ srcE,
                               const int* __restrict__ dstE, int E, int Etot) {
    int i = blockIdx.x * blockDim.x + threadIdx.x;
    if (i < Etot) {
        int s, d;
        if (i < E) { s = srcE[i]; d = dstE[i]; }
        else       { s = d = i - E; }
        int p = atomicAdd(&g_cursor[d], 1);
        g_csrsrc[p] = s;
    }
}

// ---------------- bf16 hi/lo split of x (padded to MPAD rows) ---------------
__global__ void convx_kernel(const float* __restrict__ x, int M) {
    int i = blockIdx.x * blockDim.x + threadIdx.x;   // one float4 per thread
    if (i >= MPAD * 64) return;
    int row = i >> 6;
    float4 v = make_float4(0.f, 0.f, 0.f, 0.f);
    if (row < M) v = *(const float4*)(x + (size_t)i * 4);
    __nv_bfloat16 h0 = __float2bfloat16(v.x);
    __nv_bfloat16 h1 = __float2bfloat16(v.y);
    __nv_bfloat16 h2 = __float2bfloat16(v.z);
    __nv_bfloat16 h3 = __float2bfloat16(v.w);
    __nv_bfloat162 a; a.x = h0; a.y = h1;
    __nv_bfloat162 b; b.x = h2; b.y = h3;
    *(__nv_bfloat162*)(g_xhi + (size_t)i * 4)     = a;
    *(__nv_bfloat162*)(g_xhi + (size_t)i * 4 + 2) = b;
    __nv_bfloat162 la, lb;
    la.x = __float2bfloat16(v.x - __bfloat162float(h0));
    la.y = __float2bfloat16(v.y - __bfloat162float(h1));
    lb.x = __float2bfloat16(v.z - __bfloat162float(h2));
    lb.y = __float2bfloat16(v.w - __bfloat162float(h3));
    *(__nv_bfloat162*)(g_xlo + (size_t)i * 4)     = la;
    *(__nv_bfloat162*)(g_xlo + (size_t)i * 4 + 2) = lb;
}

// ---------------- W1 transpose + split: g_b* = W1^T [n][k] ------------------
__global__ void convw_kernel(const float* __restrict__ W) {
    int i = blockIdx.x * blockDim.x + threadIdx.x;
    if (i >= 256 * 256) return;
    int n = i >> 8, k = i & 255;
    float v = W[k * 256 + n];
    __nv_bfloat16 h = __float2bfloat16(v);
    g_bhi[i] = h;
    g_blo[i] = __float2bfloat16(v - __bfloat162float(h));
}

// ---------------- GEMM1 via mma.sync bf16x3 ---------------------------------
// CTA = 128x128 output tile; 8 warps as 4(m) x 2(n); warp = 32x64.
// K=256 in 8 chunks of 32. Effective 3 passes: Ah*Bh + Ah*Bl + Al*Bh.
#define SROW 40
__global__ void __launch_bounds__(256, 1) mma1_kernel() {
    __shared__ __align__(16) __nv_bfloat16 sAhi[128 * SROW];
    __shared__ __align__(16) __nv_bfloat16 sAlo[128 * SROW];
    __shared__ __align__(16) __nv_bfloat16 sBhi[128 * SROW];
    __shared__ __align__(16) __nv_bfloat16 sBlo[128 * SROW];

    int tid = threadIdx.x;
    int lane = tid & 31, wid = tid >> 5;
    int warp_m = (wid & 3) * 32;
    int warp_n = (wid >> 2) * 64;
    int rowBase = blockIdx.y * 128;
    int colBase = blockIdx.x * 128;

    uint32_t aHiB = smem_u32(sAhi), aLoB = smem_u32(sAlo);
    uint32_t bHiB = smem_u32(sBhi), bLoB = smem_u32(sBlo);

    float acc[2][8][4];
#pragma unroll
    for (int im = 0; im < 2; im++)
#pragma unroll
        for (int jn = 0; jn < 8; jn++)
#pragma unroll
            for (int q = 0; q < 4; q++) acc[im][jn][q] = 0.f;

    uint4 pAh[2], pAl[2], pBh[2], pBl[2];
#pragma unroll
    for (int l = 0; l < 2; l++) {
        int v = tid + (l << 8);
        int r = v >> 2, cg = v & 3;
        size_t ga = (size_t)(rowBase + r) * 256 + cg * 8;
        size_t gb = (size_t)(colBase + r) * 256 + cg * 8;
        pAh[l] = *(const uint4*)(g_xhi + ga);
        pAl[l] = *(const uint4*)(g_xlo + ga);
        pBh[l] = *(const uint4*)(g_bhi + gb);
        pBl[l] = *(const uint4*)(g_blo + gb);
    }

    for (int c = 0; c < 8; c++) {
        __syncthreads();
#pragma unroll
        for (int l = 0; l < 2; l++) {
            int v = tid + (l << 8);
            int r = v >> 2, cg = v & 3;
            int so = r * SROW + cg * 8;
            *(uint4*)(sAhi + so) = pAh[l];
            *(uint4*)(sAlo + so) = pAl[l];
            *(uint4*)(sBhi + so) = pBh[l];
            *(uint4*)(sBlo + so) = pBl[l];
        }
        __syncthreads();
        if (c < 7) {
            int kk = (c + 1) * 32;
#pragma unroll
            for (int l = 0; l < 2; l++) {
                int v = tid + (l << 8);
                int r = v >> 2, cg = v & 3;
                size_t ga = (size_t)(rowBase + r) * 256 + kk + cg * 8;
                size_t gb = (size_t)(colBase + r) * 256 + kk + cg * 8;
                pAh[l] = *(const uint4*)(g_xhi + ga);
                pAl[l] = *(const uint4*)(g_xlo + ga);
                pBh[l] = *(const uint4*)(g_bhi + gb);
                pBl[l] = *(const uint4*)(g_blo + gb);
            }
        }
#pragma unroll
        for (int ks = 0; ks < 2; ks++) {
            uint32_t fAh[2][4], fAl[2][4];
#pragma unroll
            for (int im = 0; im < 2; im++) {
                uint32_t off = ((warp_m + im * 16 + (lane & 15)) * SROW +
                                ks * 16 + (lane >> 4) * 8) * 2;
                ldsm4(fAh[im], aHiB + off);
                ldsm4(fAl[im], aLoB + off);
            }
            uint32_t fBh[8][2], fBl[8][2];
#pragma unroll
            for (int j2 = 0; j2 < 4; j2++) {
                int s = lane >> 3;
                uint32_t off = ((warp_n + j2 * 16 + ((s >> 1) << 3) + (lane & 7)) * SROW +
                                ks * 16 + ((s & 1) << 3)) * 2;
                uint32_t t[4];
                ldsm4(t, bHiB + off);
                fBh[j2 * 2][0] = t[0]; fBh[j2 * 2][1] = t[1];
                fBh[j2 * 2 + 1][0] = t[2]; fBh[j2 * 2 + 1][1] = t[3];
                ldsm4(t, bLoB + off);
                fBl[j2 * 2][0] = t[0]; fBl[j2 * 2][1] = t[1];
                fBl[j2 * 2 + 1][0] = t[2]; fBl[j2 * 2 + 1][1] = t[3];
            }
#pragma unroll
            for (int im = 0; im < 2; im++)
#pragma unroll
                for (int jn = 0; jn < 8; jn++) mma_bf16(acc[im][jn], fAh[im], fBh[jn]);
#pragma unroll
            for (int im = 0; im < 2; im++)
#pragma unroll
                for (int jn = 0; jn < 8; jn++) mma_bf16(acc[im][jn], fAh[im], fBl[jn]);
#pragma unroll
            for (int im = 0; im < 2; im++)
#pragma unroll
                for (int jn = 0; jn < 8; jn++) mma_bf16(acc[im][jn], fAl[im], fBh[jn]);
        }
    }

#pragma unroll
    for (int im = 0; im < 2; im++) {
        int row0 = rowBase + warp_m + im * 16 + (lane >> 2);
#pragma unroll
        for (int jn = 0; jn < 8; jn++) {
            int col = colBase + warp_n + jn * 8 + (lane & 3) * 2;
            *(float2*)(g_h1 + (size_t)row0 * 256 + col) =
                make_float2(acc[im][jn][0], acc[im][jn][1]);
            *(float2*)(g_h1 + (size_t)(row0 + 8) * 256 + col) =
                make_float2(acc[im][jn][2], acc[im][jn][3]);
        }
    }
}

// ---------------- per-node attention logits, layer 1 -----------------------
__global__ void al1_kernel(const float* __restrict__ a_src,
                           const float* __restrict__ a_dst, int N) {
    int i = blockIdx.x * blockDim.x + threadIdx.x;
    if (i >= N * HEADS) return;
    int n = i >> 2, h = i & 3;
    const float4* hp = (const float4*)(g_h1 + (size_t)n * 256 + h * HID);
    const float4* sp = (const float4*)(a_src + h * HID);
    const float4* dp = (const float4*)(a_dst + h * HID);
    float s = 0.f, d = 0.f;
#pragma unroll
    for (int q = 0; q < HID / 4; q++) {
        float4 hv = hp[q], sv = sp[q], dv = dp[q];
        s += hv.x * sv.x + hv.y * sv.y + hv.z * sv.z + hv.w * sv.w;
        d += hv.x * dv.x + hv.y * dv.y + hv.z * dv.z + hv.w * dv.w;
    }
    g_alS1[i] = s;
    g_alD1[i] = d;
}

// ---------------- fused softmax + aggregation, layer 1 ---------------------
// one warp per (node, head); lane covers channels {2*lane, 2*lane+1}
__global__ void __launch_bounds__(256) agg1_kernel(const float* __restrict__ b1, int N) {
    int gw = blockIdx.x * 8 + (threadIdx.x >> 5);
    int lane = threadIdx.x & 31;
    if (gw >= N * HEADS) return;
    int n = gw >> 2, hh = gw & 3;
    int start = g_rowptr[n], end = g_rowptr[n + 1];
    float ad = g_alD1[n * HEADS + hh];

    float m = -INFINITY;
    for (int j = start + lane; j < end; j += 32) {
        int s = g_csrsrc[j];
        float v = g_alS1[s * HEADS + hh] + ad;
        v = (v > 0.f) ? v : 0.2f * v;
        m = fmaxf(m, v);
    }
#pragma unroll
    for (int o = 16; o; o >>= 1) m = fmaxf(m, __shfl_xor_sync(0xffffffffu, m, o));

    __shared__ float sw_w[8][32];
    __shared__ int   sw_s[8][32];
    int w = threadIdx.x >> 5;
    float acc0 = 0.f, acc1 = 0.f, ssum = 0.f;
    for (int base = start; base < end; base += 32) {
        int cnt = min(32, end - base);
        float wv = 0.f;
        if (lane < cnt) {
            int s = g_csrsrc[base + lane];
            float v = g_alS1[s * HEADS + hh] + ad;
            v = (v > 0.f) ? v : 0.2f * v;
            wv = __expf(v - m);
            sw_w[w][lane] = wv;
            sw_s[w][lane] = s;
        }
        ssum += wv;
        __syncwarp();
        for (int j = 0; j < cnt; j++) {
            float a = sw_w[w][j];
            const float2 hv = *(const float2*)(g_h1 + (size_t)sw_s[w][j] * 256 +
                                               hh * HID + 2 * lane);
            acc0 += a * hv.x;
            acc1 += a * hv.y;
        }
        __syncwarp();
    }
#pragma unroll
    for (int o = 16; o; o >>= 1) ssum += __shfl_xor_sync(0xffffffffu, ssum, o);
    float inv = 1.0f / (ssum + 1e-16f);
    float2 bv = *(const float2*)(b1 + hh * HID + 2 * lane);
    float r0 = acc0 * inv + bv.x;
    float r1 = acc1 * inv + bv.y;
    r0 = (r0 > 0.f) ? r0 : expm1f(r0);
    r1 = (r1 > 0.f) ? r1 : expm1f(r1);
    *(float2*)(g_out1 + (size_t)n * 256 + hh * HID + 2 * lane) = make_float2(r0, r1);
}

// ---------------- GEMM2: h2 = out1 @ W2  (M x 256 @ 256 x 40) --------------
__global__ void __launch_bounds__(256) gemm2_kernel(const float* __restrict__ W, int M) {
    __shared__ float Ws[256 * OUTC];  // 40 KB
    int tid = threadIdx.x;
    for (int i = tid; i < (256 * OUTC) / 4; i += 256)
        *(float4*)&Ws[i * 4] = *(const float4*)(W + i * 4);
    __syncthreads();

    int r = tid >> 3;
    int g = tid & 7;
    int grow = blockIdx.x * 32 + r;
    if (grow >= M) return;

    float acc[5] = {0.f, 0.f, 0.f, 0.f, 0.f};
    const float4* ap = (const float4*)(g_out1 + (size_t)grow * 256);
#pragma unroll 4
    for (int k4 = 0; k4 < 64; k4++) {
        float4 a4 = __ldg(&ap[k4]);
        float av[4] = {a4.x, a4.y, a4.z, a4.w};
#pragma unroll
        for (int q = 0; q < 4; q++) {
            const float* wrow = &Ws[(k4 * 4 + q) * OUTC + g * 5];
#pragma unroll
            for (int j = 0; j < 5; j++) acc[j] += av[q] * wrow[j];
        }
    }
#pragma unroll
    for (int j = 0; j < 5; j++) g_h2[(size_t)grow * OUTC + g * 5 + j] = acc[j];
}

// ---------------- per-node attention logits, layer 2 -----------------------
__global__ void al2_kernel(const float* __restrict__ a_src,
                           const float* __restrict__ a_dst, int N) {
    int n = blockIdx.x * blockDim.x + threadIdx.x;
    if (n >= N) return;
    const float4* hp = (const float4*)(g_h2 + (size_t)n * OUTC);
    const float4* sp = (const float4*)a_src;
    const float4* dp = (const float4*)a_dst;
    float s = 0.f, d = 0.f;
#pragma unroll
    for (int q = 0; q < OUTC / 4; q++) {
        float4 hv = hp[q], sv = sp[q], dv = dp[q];
        s += hv.x * sv.x + hv.y * sv.y + hv.z * sv.z + hv.w * sv.w;
        d += hv.x * dv.x + hv.y * dv.y + hv.z * dv.z + hv.w * dv.w;
    }
    g_alS2[n] = s;
    g_alD2[n] = d;
}

// ---------------- fused softmax + aggregation, layer 2 ---------------------
// one warp per node; lanes 0..19 cover channels {2*lane, 2*lane+1}
__global__ void __launch_bounds__(256) agg2_kernel(const float* __restrict__ b2,
                                                   float* __restrict__ out, int N) {
    int n = blockIdx.x * 8 + (threadIdx.x >> 5);
    int lane = threadIdx.x & 31;
    if (n >= N) return;
    int start = g_rowptr[n], end = g_rowptr[n + 1];
    float ad = g_alD2[n];

    float m = -INFINITY;
    for (int j = start + lane; j < end; j += 32) {
        int s = g_csrsrc[j];
        float v = g_alS2[s] + ad;
        v = (v > 0.f) ? v : 0.2f * v;
        m = fmaxf(m, v);
    }
#pragma unroll
    for (int o = 16; o; o >>= 1) m = fmaxf(m, __shfl_xor_sync(0xffffffffu, m, o));

    __shared__ float sw_w[8][32];
    __shared__ int   sw_s[8][32];
    int w = threadIdx.x >> 5;
    float acc0 = 0.f, acc1 = 0.f, ssum = 0.f;
    for (int base = start; base < end; base += 32) {
        int cnt = min(32, end - base);
        float wv = 0.f;
        if (lane < cnt) {
            int s = g_csrsrc[base + lane];
            float v = g_alS2[s] + ad;
            v = (v > 0.f) ? v : 0.2f * v;
            wv = __expf(v - m);
            sw_w[w][lane] = wv;
            sw_s[w][lane] = s;
        }
        ssum += wv;
        __syncwarp();
        if (lane < OUTC / 2) {
            for (int j = 0; j < cnt; j++) {
                float a = sw_w[w][j];
                const float2 hv = *(const float2*)(g_h2 + (size_t)sw_s[w][j] * OUTC +
                                                   2 * lane);
                acc0 += a * hv.x;
                acc1 += a * hv.y;
            }
        }
        __syncwarp();
    }
#pragma unroll
    for (int o = 16; o; o >>= 1) ssum += __shfl_xor_sync(0xffffffffu, ssum, o);
    float inv = 1.0f / (ssum + 1e-16f);
    if (lane < OUTC / 2) {
        float2 bv = *(const float2*)(b2 + 2 * lane);
        *(float2*)(out + (size_t)n * OUTC + 2 * lane) =
            make_float2(acc0 * inv + bv.x, acc1 * inv + bv.y);
    }
}

// ---------------- launch ----------------------------------------------------
extern "C" void kernel_launch(void* const* d_in, const int* in_sizes, int n_in,
                              void* d_out, int out_size) {
    const float* x      = (const float*)d_in[0];
    const int*   ei     = (const int*)d_in[1];
    const float* W1     = (const float*)d_in[2];
    const float* a_src1 = (const float*)d_in[3];
    const float* a_dst1 = (const float*)d_in[4];
    const float* b1     = (const float*)d_in[5];
    const float* W2     = (const float*)d_in[6];
    const float* a_src2 = (const float*)d_in[7];
    const float* a_dst2 = (const float*)d_in[8];
    const float* b2     = (const float*)d_in[9];
    float* out = (float*)d_out;

    int N = in_sizes[0] / 256;   // 50000
    int E = in_sizes[1] / 2;     // 800000
    int Etot = E + N;
    const int* srcE = ei;
    const int* dstE = ei + E;

    // side stream + events for overlapping the CSR chain with the GEMM chain.
    // Created once (resource setup, not work); captured as graph dependencies.
    static cudaStream_t sCsr = nullptr;
    static cudaEvent_t evRoot = nullptr, evCsr = nullptr;
    if (sCsr == nullptr) {
        cudaStreamCreateWithFlags(&sCsr, cudaStreamNonBlocking);
        cudaEventCreateWithFlags(&evRoot, cudaEventDisableTiming);
        cudaEventCreateWithFlags(&evCsr, cudaEventDisableTiming);
    }

    // fork: CSR build on side stream
    cudaEventRecord(evRoot, 0);
    cudaStreamWaitEvent(sCsr, evRoot, 0);
    zero_deg_kernel<<<(N + 255) / 256, 256, 0, sCsr>>>(N);
    deg_kernel<<<(Etot + 255) / 256, 256, 0, sCsr>>>(dstE, E, Etot);
    scan_kernel<<<1, 1024, 0, sCsr>>>(N);
    scatter_kernel<<<(Etot + 255) / 256, 256, 0, sCsr>>>(srcE, dstE, E, Etot);
    cudaEventRecord(evCsr, sCsr);

    // main stream: layer-1 linear chain (independent of CSR)
    convx_kernel<<<(MPAD * 64 + 255) / 256, 256>>>(x, N);
    convw_kernel<<<(256 * 256 + 255) / 256, 256>>>(W1);
    mma1_kernel<<<dim3(2, MPAD / 128), 256>>>();
    al1_kernel<<<(N * HEADS + 255) / 256, 256>>>(a_src1, a_dst1, N);

    // join: aggregation needs both chains
    cudaStreamWaitEvent(0, evCsr, 0);
    agg1_kernel<<<(N * HEADS + 7) / 8, 256>>>(b1, N);

    // layer 2
    gemm2_kernel<<<(N + 31) / 32, 256>>>(W2, N);
    al2_kernel<<<(N + 255) / 256, 256>>>(a_src2, a_dst2, N);
    agg2_kernel<<<(N + 7) / 8, 256>>>(b2, out, N);
}

// round 9
// speedup vs baseline: 1.5797x; 1.0037x over previous
#include <cuda_runtime.h>
#include <cuda_bf16.h>
#include <cuda_fp16.h>
#include <math.h>
#include <stdint.h>

#define NN    50000
#define MPAD  50048        // 391 * 128
#define EE    800000
#define HEADS 4
#define HID   64
#define OUTC  40

// ---------------- scratch (static device globals; no allocations) ----------
__device__ __half g_h1h[(size_t)MPAD * 256];  // layer-1 linear output, fp16
__device__ float g_out1[(size_t)NN * 256];    // layer-1 GAT output after ELU
__device__ float g_h2  [(size_t)NN * OUTC];   // layer-2 linear output
__device__ float g_alS1[NN * HEADS];
__device__ float g_alD1[NN * HEADS];
__device__ float g_alS2[NN];
__device__ float g_alD2[NN];
__device__ int   g_deg   [NN];
__device__ int   g_rowptr[NN + 1];
__device__ int   g_cursor[NN];
__device__ int   g_csrsrc[EE + NN];
// bf16x3 split operands for tensor-core GEMM1
__device__ __nv_bfloat16 g_xhi[(size_t)MPAD * 256];
__device__ __nv_bfloat16 g_xlo[(size_t)MPAD * 256];
__device__ __nv_bfloat16 g_bhi[256 * 256];   // W1^T  [N=256][K=256]
__device__ __nv_bfloat16 g_blo[256 * 256];

// ---------------- PTX helpers (portable sm_80+ instructions only) ----------
__device__ __forceinline__ uint32_t smem_u32(const void* p) {
    uint32_t a;
    asm("{ .reg .u64 t; cvta.to.shared.u64 t, %1; cvt.u32.u64 %0, t; }" : "=r"(a) : "l"(p));
    return a;
}
__device__ __forceinline__ void ldsm4(uint32_t* r, uint32_t addr) {
    asm volatile("ldmatrix.sync.aligned.m8n8.x4.shared.b16 {%0,%1,%2,%3}, [%4];"
                 : "=r"(r[0]), "=r"(r[1]), "=r"(r[2]), "=r"(r[3]) : "r"(addr));
}
__device__ __forceinline__ void mma_bf16(float* c, const uint32_t* a, const uint32_t* b) {
    asm volatile(
        "mma.sync.aligned.m16n8k16.row.col.f32.bf16.bf16.f32 "
        "{%0,%1,%2,%3}, {%4,%5,%6,%7}, {%8,%9}, {%0,%1,%2,%3};"
        : "+f"(c[0]), "+f"(c[1]), "+f"(c[2]), "+f"(c[3])
        : "r"(a[0]), "r"(a[1]), "r"(a[2]), "r"(a[3]), "r"(b[0]), "r"(b[1]));
}

// ---------------- CSR build ------------------------------------------------
__global__ void zero_deg_kernel(int n) {
    int i = blockIdx.x * blockDim.x + threadIdx.x;
    if (i < n) g_deg[i] = 0;
}

__global__ void deg_kernel(const int* __restrict__ dstE, int E, int Etot) {
    int i = blockIdx.x * blockDim.x + threadIdx.x;
    if (i < Etot) {
        int d = (i < E) ? dstE[i] : (i - E);   // self-loop for i >= E
        atomicAdd(&g_deg[d], 1);
    }
}

__global__ void scan_kernel(int n) {
    __shared__ int sums[1024];
    int tid = threadIdx.x;
    int chunk = (n + 1023) / 1024;
    int start = tid * chunk;
    int end = min(start + chunk, n);
    int s = 0;
    for (int i = start; i < end; i++) s += g_deg[i];
    sums[tid] = s;
    __syncthreads();
    for (int off = 1; off < 1024; off <<= 1) {
        int v = (tid >= off) ? sums[tid - off] : 0;
        __syncthreads();
        sums[tid] += v;
        __syncthreads();
    }
    int base = (tid > 0) ? sums[tid - 1] : 0;
    for (int i = start; i < end; i++) {
        g_rowptr[i] = base;
        g_cursor[i] = base;
        base += g_deg[i];
    }
    if (tid == 1023) g_rowptr[n] = base;
}

__global__ void scatter_kernel(const int* __restrict__ srcE,
                               const int* __restrict__ dstE, int E, int Etot) {
    int i = blockIdx.x * blockDim.x + threadIdx.x;
    if (i < Etot) {
        int s, d;
        if (i < E) { s = srcE[i]; d = dstE[i]; }
        else       { s = d = i - E; }
        int p = atomicAdd(&g_cursor[d], 1);
        g_csrsrc[p] = s;
    }
}

// ---------------- bf16 hi/lo split of x (padded to MPAD rows) ---------------
__global__ void convx_kernel(const float* __restrict__ x, int M) {
    int i = blockIdx.x * blockDim.x + threadIdx.x;   // one float4 per thread
    if (i >= MPAD * 64) return;
    int row = i >> 6;
    float4 v = make_float4(0.f, 0.f, 0.f, 0.f);
    if (row < M) v = *(const float4*)(x + (size_t)i * 4);
    __nv_bfloat16 h0 = __float2bfloat16(v.x);
    __nv_bfloat16 h1 = __float2bfloat16(v.y);
    __nv_bfloat16 h2 = __float2bfloat16(v.z);
    __nv_bfloat16 h3 = __float2bfloat16(v.w);
    __nv_bfloat162 a; a.x = h0; a.y = h1;
    __nv_bfloat162 b; b.x = h2; b.y = h3;
    *(__nv_bfloat162*)(g_xhi + (size_t)i * 4)     = a;
    *(__nv_bfloat162*)(g_xhi + (size_t)i * 4 + 2) = b;
    __nv_bfloat162 la, lb;
    la.x = __float2bfloat16(v.x - __bfloat162float(h0));
    la.y = __float2bfloat16(v.y - __bfloat162float(h1));
    lb.x = __float2bfloat16(v.z - __bfloat162float(h2));
    lb.y = __float2bfloat16(v.w - __bfloat162float(h3));
    *(__nv_bfloat162*)(g_xlo + (size_t)i * 4)     = la;
    *(__nv_bfloat162*)(g_xlo + (size_t)i * 4 + 2) = lb;
}

// ---------------- W1 transpose + split: g_b* = W1^T [n][k] ------------------
__global__ void convw_kernel(const float* __restrict__ W) {
    int i = blockIdx.x * blockDim.x + threadIdx.x;
    if (i >= 256 * 256) return;
    int n = i >> 8, k = i & 255;
    float v = W[k * 256 + n];
    __nv_bfloat16 h = __float2bfloat16(v);
    g_bhi[i] = h;
    g_blo[i] = __float2bfloat16(v - __bfloat162float(h));
}

// ---------------- GEMM1 via mma.sync bf16x3, fp16 output -------------------
// CTA = 128x128 output tile; 8 warps as 4(m) x 2(n); warp = 32x64.
// K=256 in 8 chunks of 32. Effective 3 passes: Ah*Bh + Ah*Bl + Al*Bh.
#define SROW 40
__global__ void __launch_bounds__(256, 1) mma1_kernel() {
    __shared__ __align__(16) __nv_bfloat16 sAhi[128 * SROW];
    __shared__ __align__(16) __nv_bfloat16 sAlo[128 * SROW];
    __shared__ __align__(16) __nv_bfloat16 sBhi[128 * SROW];
    __shared__ __align__(16) __nv_bfloat16 sBlo[128 * SROW];

    int tid = threadIdx.x;
    int lane = tid & 31, wid = tid >> 5;
    int warp_m = (wid & 3) * 32;
    int warp_n = (wid >> 2) * 64;
    int rowBase = blockIdx.y * 128;
    int colBase = blockIdx.x * 128;

    uint32_t aHiB = smem_u32(sAhi), aLoB = smem_u32(sAlo);
    uint32_t bHiB = smem_u32(sBhi), bLoB = smem_u32(sBlo);

    float acc[2][8][4];
#pragma unroll
    for (int im = 0; im < 2; im++)
#pragma unroll
        for (int jn = 0; jn < 8; jn++)
#pragma unroll
            for (int q = 0; q < 4; q++) acc[im][jn][q] = 0.f;

    uint4 pAh[2], pAl[2], pBh[2], pBl[2];
#pragma unroll
    for (int l = 0; l < 2; l++) {
        int v = tid + (l << 8);
        int r = v >> 2, cg = v & 3;
        size_t ga = (size_t)(rowBase + r) * 256 + cg * 8;
        size_t gb = (size_t)(colBase + r) * 256 + cg * 8;
        pAh[l] = *(const uint4*)(g_xhi + ga);
        pAl[l] = *(const uint4*)(g_xlo + ga);
        pBh[l] = *(const uint4*)(g_bhi + gb);
        pBl[l] = *(const uint4*)(g_blo + gb);
    }

    for (int c = 0; c < 8; c++) {
        __syncthreads();
#pragma unroll
        for (int l = 0; l < 2; l++) {
            int v = tid + (l << 8);
            int r = v >> 2, cg = v & 3;
            int so = r * SROW + cg * 8;
            *(uint4*)(sAhi + so) = pAh[l];
            *(uint4*)(sAlo + so) = pAl[l];
            *(uint4*)(sBhi + so) = pBh[l];
            *(uint4*)(sBlo + so) = pBl[l];
        }
        __syncthreads();
        if (c < 7) {
            int kk = (c + 1) * 32;
#pragma unroll
            for (int l = 0; l < 2; l++) {
                int v = tid + (l << 8);
                int r = v >> 2, cg = v & 3;
                size_t ga = (size_t)(rowBase + r) * 256 + kk + cg * 8;
                size_t gb = (size_t)(colBase + r) * 256 + kk + cg * 8;
                pAh[l] = *(const uint4*)(g_xhi + ga);
                pAl[l] = *(const uint4*)(g_xlo + ga);
                pBh[l] = *(const uint4*)(g_bhi + gb);
                pBl[l] = *(const uint4*)(g_blo + gb);
            }
        }
#pragma unroll
        for (int ks = 0; ks < 2; ks++) {
            uint32_t fAh[2][4], fAl[2][4];
#pragma unroll
            for (int im = 0; im < 2; im++) {
                uint32_t off = ((warp_m + im * 16 + (lane & 15)) * SROW +
                                ks * 16 + (lane >> 4) * 8) * 2;
                ldsm4(fAh[im], aHiB + off);
                ldsm4(fAl[im], aLoB + off);
            }
            uint32_t fBh[8][2], fBl[8][2];
#pragma unroll
            for (int j2 = 0; j2 < 4; j2++) {
                int s = lane >> 3;
                uint32_t off = ((warp_n + j2 * 16 + ((s >> 1) << 3) + (lane & 7)) * SROW +
                                ks * 16 + ((s & 1) << 3)) * 2;
                uint32_t t[4];
                ldsm4(t, bHiB + off);
                fBh[j2 * 2][0] = t[0]; fBh[j2 * 2][1] = t[1];
                fBh[j2 * 2 + 1][0] = t[2]; fBh[j2 * 2 + 1][1] = t[3];
                ldsm4(t, bLoB + off);
                fBl[j2 * 2][0] = t[0]; fBl[j2 * 2][1] = t[1];
                fBl[j2 * 2 + 1][0] = t[2]; fBl[j2 * 2 + 1][1] = t[3];
            }
#pragma unroll
            for (int im = 0; im < 2; im++)
#pragma unroll
                for (int jn = 0; jn < 8; jn++) mma_bf16(acc[im][jn], fAh[im], fBh[jn]);
#pragma unroll
            for (int im = 0; im < 2; im++)
#pragma unroll
                for (int jn = 0; jn < 8; jn++) mma_bf16(acc[im][jn], fAh[im], fBl[jn]);
#pragma unroll
            for (int im = 0; im < 2; im++)
#pragma unroll
                for (int jn = 0; jn < 8; jn++) mma_bf16(acc[im][jn], fAl[im], fBh[jn]);
        }
    }

    // epilogue: fp32 acc -> fp16 (half2) stores
#pragma unroll
    for (int im = 0; im < 2; im++) {
        int row0 = rowBase + warp_m + im * 16 + (lane >> 2);
#pragma unroll
        for (int jn = 0; jn < 8; jn++) {
            int col = colBase + warp_n + jn * 8 + (lane & 3) * 2;
            *(__half2*)(g_h1h + (size_t)row0 * 256 + col) =
                __floats2half2_rn(acc[im][jn][0], acc[im][jn][1]);
            *(__half2*)(g_h1h + (size_t)(row0 + 8) * 256 + col) =
                __floats2half2_rn(acc[im][jn][2], acc[im][jn][3]);
        }
    }
}

// ---------------- per-node attention logits, layer 1 (fp16 h) ---------------
__global__ void al1_kernel(const float* __restrict__ a_src,
                           const float* __restrict__ a_dst, int N) {
    int i = blockIdx.x * blockDim.x + threadIdx.x;
    if (i >= N * HEADS) return;
    int n = i >> 2, h = i & 3;
    const uint4* hp = (const uint4*)(g_h1h + (size_t)n * 256 + h * HID);  // 8 halves each
    const float* sp = a_src + h * HID;
    const float* dp = a_dst + h * HID;
    float s = 0.f, d = 0.f;
#pragma unroll
    for (int q = 0; q < HID / 8; q++) {
        uint4 u = hp[q];
        float2 f0 = __half22float2(*(const __half2*)&u.x);
        float2 f1 = __half22float2(*(const __half2*)&u.y);
        float2 f2 = __half22float2(*(const __half2*)&u.z);
        float2 f3 = __half22float2(*(const __half2*)&u.w);
        float hv[8] = {f0.x, f0.y, f1.x, f1.y, f2.x, f2.y, f3.x, f3.y};
#pragma unroll
        for (int t = 0; t < 8; t++) {
            s += hv[t] * sp[q * 8 + t];
            d += hv[t] * dp[q * 8 + t];
        }
    }
    g_alS1[i] = s;
    g_alD1[i] = d;
}

// ---------------- fused softmax + aggregation, layer 1 (fp16 gather) --------
// one warp per (node, head); lane covers channels {2*lane, 2*lane+1}
__global__ void __launch_bounds__(256) agg1_kernel(const float* __restrict__ b1, int N) {
    int gw = blockIdx.x * 8 + (threadIdx.x >> 5);
    int lane = threadIdx.x & 31;
    if (gw >= N * HEADS) return;
    int n = gw >> 2, hh = gw & 3;
    int start = g_rowptr[n], end = g_rowptr[n + 1];
    float ad = g_alD1[n * HEADS + hh];

    float m = -INFINITY;
    for (int j = start + lane; j < end; j += 32) {
        int s = g_csrsrc[j];
        float v = g_alS1[s * HEADS + hh] + ad;
        v = (v > 0.f) ? v : 0.2f * v;
        m = fmaxf(m, v);
    }
#pragma unroll
    for (int o = 16; o; o >>= 1) m = fmaxf(m, __shfl_xor_sync(0xffffffffu, m, o));

    __shared__ float sw_w[8][32];
    __shared__ int   sw_s[8][32];
    int w = threadIdx.x >> 5;
    float acc0 = 0.f, acc1 = 0.f, ssum = 0.f;
    for (int base = start; base < end; base += 32) {
        int cnt = min(32, end - base);
        float wv = 0.f;
        if (lane < cnt) {
            int s = g_csrsrc[base + lane];
            float v = g_alS1[s * HEADS + hh] + ad;
            v = (v > 0.f) ? v : 0.2f * v;
            wv = __expf(v - m);
            sw_w[w][lane] = wv;
            sw_s[w][lane] = s;
        }
        ssum += wv;
        __syncwarp();
        for (int j = 0; j < cnt; j++) {
            float a = sw_w[w][j];
            __half2 hv2 = *(const __half2*)(g_h1h + (size_t)sw_s[w][j] * 256 +
                                            hh * HID + 2 * lane);
            float2 f = __half22float2(hv2);
            acc0 += a * f.x;
            acc1 += a * f.y;
        }
        __syncwarp();
    }
#pragma unroll
    for (int o = 16; o; o >>= 1) ssum += __shfl_xor_sync(0xffffffffu, ssum, o);
    float inv = 1.0f / (ssum + 1e-16f);
    float2 bv = *(const float2*)(b1 + hh * HID + 2 * lane);
    float r0 = acc0 * inv + bv.x;
    float r1 = acc1 * inv + bv.y;
    r0 = (r0 > 0.f) ? r0 : expm1f(r0);
    r1 = (r1 > 0.f) ? r1 : expm1f(r1);
    *(float2*)(g_out1 + (size_t)n * 256 + hh * HID + 2 * lane) = make_float2(r0, r1);
}

// ---------------- GEMM2 + fused layer-2 logits ------------------------------
// W2 cached in smem; 32 rows/block; thread computes 5 outputs; 8-lane shfl
// reduction produces alS2/alD2 in the same kernel (al2 kernel deleted).
__global__ void __launch_bounds__(256) gemm2_kernel(const float* __restrict__ W,
                                                    const float* __restrict__ as2,
                                                    const float* __restrict__ ad2, int M) {
    __shared__ float Ws[256 * OUTC];  // 40 KB
    int tid = threadIdx.x;
    for (int i = tid; i < (256 * OUTC) / 4; i += 256)
        *(float4*)&Ws[i * 4] = *(const float4*)(W + i * 4);
    __syncthreads();

    int r = tid >> 3;
    int g = tid & 7;
    int grow = blockIdx.x * 32 + r;
    if (grow >= M) return;

    float acc[5] = {0.f, 0.f, 0.f, 0.f, 0.f};
    const float4* ap = (const float4*)(g_out1 + (size_t)grow * 256);
#pragma unroll 4
    for (int k4 = 0; k4 < 64; k4++) {
        float4 a4 = __ldg(&ap[k4]);
        float av[4] = {a4.x, a4.y, a4.z, a4.w};
#pragma unroll
        for (int q = 0; q < 4; q++) {
            const float* wrow = &Ws[(k4 * 4 + q) * OUTC + g * 5];
#pragma unroll
            for (int j = 0; j < 5; j++) acc[j] += av[q] * wrow[j];
        }
    }
    float s = 0.f, d = 0.f;
#pragma unroll
    for (int j = 0; j < 5; j++) {
        g_h2[(size_t)grow * OUTC + g * 5 + j] = acc[j];
        s += acc[j] * __ldg(as2 + g * 5 + j);
        d += acc[j] * __ldg(ad2 + g * 5 + j);
    }
#pragma unroll
    for (int o = 4; o; o >>= 1) {
        s += __shfl_xor_sync(0xffffffffu, s, o);
        d += __shfl_xor_sync(0xffffffffu, d, o);
    }
    if (g == 0) {
        g_alS2[grow] = s;
        g_alD2[grow] = d;
    }
}

// ---------------- fused softmax + aggregation, layer 2 ---------------------
// one warp per node; lanes 0..19 cover channels {2*lane, 2*lane+1}
__global__ void __launch_bounds__(256) agg2_kernel(const float* __restrict__ b2,
                                                   float* __restrict__ out, int N) {
    int n = blockIdx.x * 8 + (threadIdx.x >> 5);
    int lane = threadIdx.x & 31;
    if (n >= N) return;
    int start = g_rowptr[n], end = g_rowptr[n + 1];
    float ad = g_alD2[n];

    float m = -INFINITY;
    for (int j = start + lane; j < end; j += 32) {
        int s = g_csrsrc[j];
        float v = g_alS2[s] + ad;
        v = (v > 0.f) ? v : 0.2f * v;
        m = fmaxf(m, v);
    }
#pragma unroll
    for (int o = 16; o; o >>= 1) m = fmaxf(m, __shfl_xor_sync(0xffffffffu, m, o));

    __shared__ float sw_w[8][32];
    __shared__ int   sw_s[8][32];
    int w = threadIdx.x >> 5;
    float acc0 = 0.f, acc1 = 0.f, ssum = 0.f;
    for (int base = start; base < end; base += 32) {
        int cnt = min(32, end - base);
        float wv = 0.f;
        if (lane < cnt) {
            int s = g_csrsrc[base + lane];
            float v = g_alS2[s] + ad;
            v = (v > 0.f) ? v : 0.2f * v;
            wv = __expf(v - m);
            sw_w[w][lane] = wv;
            sw_s[w][lane] = s;
        }
        ssum += wv;
        __syncwarp();
        if (lane < OUTC / 2) {
            for (int j = 0; j < cnt; j++) {
                float a = sw_w[w][j];
                const float2 hv = *(const float2*)(g_h2 + (size_t)sw_s[w][j] * OUTC +
                                                   2 * lane);
                acc0 += a * hv.x;
                acc1 += a * hv.y;
            }
        }
        __syncwarp();
    }
#pragma unroll
    for (int o = 16; o; o >>= 1) ssum += __shfl_xor_sync(0xffffffffu, ssum, o);
    float inv = 1.0f / (ssum + 1e-16f);
    if (lane < OUTC / 2) {
        float2 bv = *(const float2*)(b2 + 2 * lane);
        *(float2*)(out + (size_t)n * OUTC + 2 * lane) =
            make_float2(acc0 * inv + bv.x, acc1 * inv + bv.y);
    }
}

// ---------------- launch ----------------------------------------------------
extern "C" void kernel_launch(void* const* d_in, const int* in_sizes, int n_in,
                              void* d_out, int out_size) {
    const float* x      = (const float*)d_in[0];
    const int*   ei     = (const int*)d_in[1];
    const float* W1     = (const float*)d_in[2];
    const float* a_src1 = (const float*)d_in[3];
    const float* a_dst1 = (const float*)d_in[4];
    const float* b1     = (const float*)d_in[5];
    const float* W2     = (const float*)d_in[6];
    const float* a_src2 = (const float*)d_in[7];
    const float* a_dst2 = (const float*)d_in[8];
    const float* b2     = (const float*)d_in[9];
    float* out = (float*)d_out;

    int N = in_sizes[0] / 256;   // 50000
    int E = in_sizes[1] / 2;     // 800000
    int Etot = E + N;
    const int* srcE = ei;
    const int* dstE = ei + E;

    // side stream + events for overlapping the CSR chain with the GEMM chain.
    static cudaStream_t sCsr = nullptr;
    static cudaEvent_t evRoot = nullptr, evCsr = nullptr;
    if (sCsr == nullptr) {
        cudaStreamCreateWithFlags(&sCsr, cudaStreamNonBlocking);
        cudaEventCreateWithFlags(&evRoot, cudaEventDisableTiming);
        cudaEventCreateWithFlags(&evCsr, cudaEventDisableTiming);
    }

    // fork: CSR build on side stream
    cudaEventRecord(evRoot, 0);
    cudaStreamWaitEvent(sCsr, evRoot, 0);
    zero_deg_kernel<<<(N + 255) / 256, 256, 0, sCsr>>>(N);
    deg_kernel<<<(Etot + 255) / 256, 256, 0, sCsr>>>(dstE, E, Etot);
    scan_kernel<<<1, 1024, 0, sCsr>>>(N);
    scatter_kernel<<<(Etot + 255) / 256, 256, 0, sCsr>>>(srcE, dstE, E, Etot);
    cudaEventRecord(evCsr, sCsr);

    // main stream: layer-1 linear chain (independent of CSR)
    convx_kernel<<<(MPAD * 64 + 255) / 256, 256>>>(x, N);
    convw_kernel<<<(256 * 256 + 255) / 256, 256>>>(W1);
    mma1_kernel<<<dim3(2, MPAD / 128), 256>>>();
    al1_kernel<<<(N * HEADS + 255) / 256, 256>>>(a_src1, a_dst1, N);

    // join: aggregation needs both chains
    cudaStreamWaitEvent(0, evCsr, 0);
    agg1_kernel<<<(N * HEADS + 7) / 8, 256>>>(b1, N);

    // layer 2
    gemm2_kernel<<<(N + 31) / 32, 256>>>(W2, a_src2, a_dst2, N);
    agg2_kernel<<<(N + 7) / 8, 256>>>(b2, out, N);
}

// round 12
// speedup vs baseline: 1.6129x; 1.0210x over previous
#include <cuda_runtime.h>
#include <cuda_bf16.h>
#include <cuda_fp16.h>
#include <math.h>
#include <stdint.h>

#define NN    50000
#define MPAD  50048        // 391 * 128
#define EE    800000
#define HEADS 4
#define HID   64
#define OUTC  40

// ---------------- scratch (static device globals; no allocations) ----------
__device__ __half g_h1h[(size_t)MPAD * 256];  // layer-1 linear output, fp16
__device__ float g_out1[(size_t)NN * 256];    // layer-1 GAT output after ELU
__device__ float g_h2  [(size_t)NN * OUTC];   // layer-2 linear output
__device__ float g_alS1[NN * HEADS];
__device__ float g_alD1[NN * HEADS];
__device__ float g_alS2[NN];
__device__ float g_alD2[NN];
__device__ unsigned g_mS1[HEADS];             // global max of alS1 per head (flipped uint)
__device__ unsigned g_mS2;                    // global max of alS2
__device__ int   g_deg   [NN];
__device__ int   g_rowptr[NN + 1];
__device__ int   g_cursor[NN];
__device__ int   g_csrsrc[EE + NN];
// bf16x3 split operands for tensor-core GEMM1
__device__ __nv_bfloat16 g_xhi[(size_t)MPAD * 256];
__device__ __nv_bfloat16 g_xlo[(size_t)MPAD * 256];
__device__ __nv_bfloat16 g_bhi[256 * 256];   // W1^T  [N=256][K=256]
__device__ __nv_bfloat16 g_blo[256 * 256];

// ---------------- helpers ---------------------------------------------------
__device__ __forceinline__ unsigned fl_f2u(float f) {   // order-preserving float->uint
    unsigned u = __float_as_uint(f);
    return (u & 0x80000000u) ? ~u : (u | 0x80000000u);
}
__device__ __forceinline__ float fl_u2f(unsigned u) {
    return __uint_as_float((u & 0x80000000u) ? (u & 0x7fffffffu) : ~u);
}
__device__ __forceinline__ uint32_t smem_u32(const void* p) {
    uint32_t a;
    asm("{ .reg .u64 t; cvta.to.shared.u64 t, %1; cvt.u32.u64 %0, t; }" : "=r"(a) : "l"(p));
    return a;
}
__device__ __forceinline__ void ldsm4(uint32_t* r, uint32_t addr) {
    asm volatile("ldmatrix.sync.aligned.m8n8.x4.shared.b16 {%0,%1,%2,%3}, [%4];"
                 : "=r"(r[0]), "=r"(r[1]), "=r"(r[2]), "=r"(r[3]) : "r"(addr));
}
__device__ __forceinline__ void mma_bf16(float* c, const uint32_t* a, const uint32_t* b) {
    asm volatile(
        "mma.sync.aligned.m16n8k16.row.col.f32.bf16.bf16.f32 "
        "{%0,%1,%2,%3}, {%4,%5,%6,%7}, {%8,%9}, {%0,%1,%2,%3};"
        : "+f"(c[0]), "+f"(c[1]), "+f"(c[2]), "+f"(c[3])
        : "r"(a[0]), "r"(a[1]), "r"(a[2]), "r"(a[3]), "r"(b[0]), "r"(b[1]));
}

// ---------------- CSR build ------------------------------------------------
__global__ void zero_deg_kernel(int n) {
    int i = blockIdx.x * blockDim.x + threadIdx.x;
    if (i < n) g_deg[i] = 0;
}

__global__ void deg_kernel(const int* __restrict__ dstE, int E, int Etot) {
    int i = blockIdx.x * blockDim.x + threadIdx.x;
    if (i < Etot) {
        int d = (i < E) ? dstE[i] : (i - E);   // self-loop for i >= E
        atomicAdd(&g_deg[d], 1);
    }
}

__global__ void scan_kernel(int n) {
    __shared__ int sums[1024];
    int tid = threadIdx.x;
    int chunk = (n + 1023) / 1024;
    int start = tid * chunk;
    int end = min(start + chunk, n);
    int s = 0;
    for (int i = start; i < end; i++) s += g_deg[i];
    sums[tid] = s;
    __syncthreads();
    for (int off = 1; off < 1024; off <<= 1) {
        int v = (tid >= off) ? sums[tid - off] : 0;
        __syncthreads();
        sums[tid] += v;
        __syncthreads();
    }
    int base = (tid > 0) ? sums[tid - 1] : 0;
    for (int i = start; i < end; i++) {
        g_rowptr[i] = base;
        g_cursor[i] = base;
        base += g_deg[i];
    }
    if (tid == 1023) g_rowptr[n] = base;
}

__global__ void scatter_kernel(const int* __restrict__ srcE,
                               const int* __restrict__ dstE, int E, int Etot) {
    int i = blockIdx.x * blockDim.x + threadIdx.x;
    if (i < Etot) {
        int s, d;
        if (i < E) { s = srcE[i]; d = dstE[i]; }
        else       { s = d = i - E; }
        int p = atomicAdd(&g_cursor[d], 1);
        g_csrsrc[p] = s;
    }
}

// ---------------- bf16 hi/lo split of x (padded to MPAD rows) ---------------
__global__ void convx_kernel(const float* __restrict__ x, int M) {
    int i = blockIdx.x * blockDim.x + threadIdx.x;   // one float4 per thread
    if (i >= MPAD * 64) return;
    int row = i >> 6;
    float4 v = make_float4(0.f, 0.f, 0.f, 0.f);
    if (row < M) v = *(const float4*)(x + (size_t)i * 4);
    __nv_bfloat16 h0 = __float2bfloat16(v.x);
    __nv_bfloat16 h1 = __float2bfloat16(v.y);
    __nv_bfloat16 h2 = __float2bfloat16(v.z);
    __nv_bfloat16 h3 = __float2bfloat16(v.w);
    __nv_bfloat162 a; a.x = h0; a.y = h1;
    __nv_bfloat162 b; b.x = h2; b.y = h3;
    *(__nv_bfloat162*)(g_xhi + (size_t)i * 4)     = a;
    *(__nv_bfloat162*)(g_xhi + (size_t)i * 4 + 2) = b;
    __nv_bfloat162 la, lb;
    la.x = __float2bfloat16(v.x - __bfloat162float(h0));
    la.y = __float2bfloat16(v.y - __bfloat162float(h1));
    lb.x = __float2bfloat16(v.z - __bfloat162float(h2));
    lb.y = __float2bfloat16(v.w - __bfloat162float(h3));
    *(__nv_bfloat162*)(g_xlo + (size_t)i * 4)     = la;
    *(__nv_bfloat162*)(g_xlo + (size_t)i * 4 + 2) = lb;
}

// ---------------- W1 transpose + split (also resets global-max cells) -------
__global__ void convw_kernel(const float* __restrict__ W) {
    int i = blockIdx.x * blockDim.x + threadIdx.x;
    if (i < HEADS) g_mS1[i] = 0u;        // reset before al1's atomicMax
    if (i == HEADS) g_mS2 = 0u;          // reset before gemm2's atomicMax
    if (i >= 256 * 256) return;
    int n = i >> 8, k = i & 255;
    float v = W[k * 256 + n];
    __nv_bfloat16 h = __float2bfloat16(v);
    g_bhi[i] = h;
    g_blo[i] = __float2bfloat16(v - __bfloat162float(h));
}

// ---------------- GEMM1 via mma.sync bf16x3, fp16 output -------------------
#define SROW 40
__global__ void __launch_bounds__(256, 1) mma1_kernel() {
    __shared__ __align__(16) __nv_bfloat16 sAhi[128 * SROW];
    __shared__ __align__(16) __nv_bfloat16 sAlo[128 * SROW];
    __shared__ __align__(16) __nv_bfloat16 sBhi[128 * SROW];
    __shared__ __align__(16) __nv_bfloat16 sBlo[128 * SROW];

    int tid = threadIdx.x;
    int lane = tid & 31, wid = tid >> 5;
    int warp_m = (wid & 3) * 32;
    int warp_n = (wid >> 2) * 64;
    int rowBase = blockIdx.y * 128;
    int colBase = blockIdx.x * 128;

    uint32_t aHiB = smem_u32(sAhi), aLoB = smem_u32(sAlo);
    uint32_t bHiB = smem_u32(sBhi), bLoB = smem_u32(sBlo);

    float acc[2][8][4];
#pragma unroll
    for (int im = 0; im < 2; im++)
#pragma unroll
        for (int jn = 0; jn < 8; jn++)
#pragma unroll
            for (int q = 0; q < 4; q++) acc[im][jn][q] = 0.f;

    uint4 pAh[2], pAl[2], pBh[2], pBl[2];
#pragma unroll
    for (int l = 0; l < 2; l++) {
        int v = tid + (l << 8);
        int r = v >> 2, cg = v & 3;
        size_t ga = (size_t)(rowBase + r) * 256 + cg * 8;
        size_t gb = (size_t)(colBase + r) * 256 + cg * 8;
        pAh[l] = *(const uint4*)(g_xhi + ga);
        pAl[l] = *(const uint4*)(g_xlo + ga);
        pBh[l] = *(const uint4*)(g_bhi + gb);
        pBl[l] = *(const uint4*)(g_blo + gb);
    }

    for (int c = 0; c < 8; c++) {
        __syncthreads();
#pragma unroll
        for (int l = 0; l < 2; l++) {
            int v = tid + (l << 8);
            int r = v >> 2, cg = v & 3;
            int so = r * SROW + cg * 8;
            *(uint4*)(sAhi + so) = pAh[l];
            *(uint4*)(sAlo + so) = pAl[l];
            *(uint4*)(sBhi + so) = pBh[l];
            *(uint4*)(sBlo + so) = pBl[l];
        }
        __syncthreads();
        if (c < 7) {
            int kk = (c + 1) * 32;
#pragma unroll
            for (int l = 0; l < 2; l++) {
                int v = tid + (l << 8);
                int r = v >> 2, cg = v & 3;
                size_t ga = (size_t)(rowBase + r) * 256 + kk + cg * 8;
                size_t gb = (size_t)(colBase + r) * 256 + kk + cg * 8;
                pAh[l] = *(const uint4*)(g_xhi + ga);
                pAl[l] = *(const uint4*)(g_xlo + ga);
                pBh[l] = *(const uint4*)(g_bhi + gb);
                pBl[l] = *(const uint4*)(g_blo + gb);
            }
        }
#pragma unroll
        for (int ks = 0; ks < 2; ks++) {
            uint32_t fAh[2][4], fAl[2][4];
#pragma unroll
            for (int im = 0; im < 2; im++) {
                uint32_t off = ((warp_m + im * 16 + (lane & 15)) * SROW +
                                ks * 16 + (lane >> 4) * 8) * 2;
                ldsm4(fAh[im], aHiB + off);
                ldsm4(fAl[im], aLoB + off);
            }
            uint32_t fBh[8][2], fBl[8][2];
#pragma unroll
            for (int j2 = 0; j2 < 4; j2++) {
                int s = lane >> 3;
                uint32_t off = ((warp_n + j2 * 16 + ((s >> 1) << 3) + (lane & 7)) * SROW +
                                ks * 16 + ((s & 1) << 3)) * 2;
                uint32_t t[4];
                ldsm4(t, bHiB + off);
                fBh[j2 * 2][0] = t[0]; fBh[j2 * 2][1] = t[1];
                fBh[j2 * 2 + 1][0] = t[2]; fBh[j2 * 2 + 1][1] = t[3];
                ldsm4(t, bLoB + off);
                fBl[j2 * 2][0] = t[0]; fBl[j2 * 2][1] = t[1];
                fBl[j2 * 2 + 1][0] = t[2]; fBl[j2 * 2 + 1][1] = t[3];
            }
#pragma unroll
            for (int im = 0; im < 2; im++)
#pragma unroll
                for (int jn = 0; jn < 8; jn++) mma_bf16(acc[im][jn], fAh[im], fBh[jn]);
#pragma unroll
            for (int im = 0; im < 2; im++)
#pragma unroll
                for (int jn = 0; jn < 8; jn++) mma_bf16(acc[im][jn], fAh[im], fBl[jn]);
#pragma unroll
            for (int im = 0; im < 2; im++)
#pragma unroll
                for (int jn = 0; jn < 8; jn++) mma_bf16(acc[im][jn], fAl[im], fBh[jn]);
        }
    }

#pragma unroll
    for (int im = 0; im < 2; im++) {
        int row0 = rowBase + warp_m + im * 16 + (lane >> 2);
#pragma unroll
        for (int jn = 0; jn < 8; jn++) {
            int col = colBase + warp_n + jn * 8 + (lane & 3) * 2;
            *(__half2*)(g_h1h + (size_t)row0 * 256 + col) =
                __floats2half2_rn(acc[im][jn][0], acc[im][jn][1]);
            *(__half2*)(g_h1h + (size_t)(row0 + 8) * 256 + col) =
                __floats2half2_rn(acc[im][jn][2], acc[im][jn][3]);
        }
    }
}

// ---------------- per-node attention logits, layer 1 (+ global max) --------
__global__ void al1_kernel(const float* __restrict__ a_src,
                           const float* __restrict__ a_dst, int N) {
    int i = blockIdx.x * blockDim.x + threadIdx.x;
    if (i >= N * HEADS) return;
    int n = i >> 2, h = i & 3;
    const uint4* hp = (const uint4*)(g_h1h + (size_t)n * 256 + h * HID);
    const float* sp = a_src + h * HID;
    const float* dp = a_dst + h * HID;
    float s = 0.f, d = 0.f;
#pragma unroll
    for (int q = 0; q < HID / 8; q++) {
        uint4 u = hp[q];
        float2 f0 = __half22float2(*(const __half2*)&u.x);
        float2 f1 = __half22float2(*(const __half2*)&u.y);
        float2 f2 = __half22float2(*(const __half2*)&u.z);
        float2 f3 = __half22float2(*(const __half2*)&u.w);
        float hv[8] = {f0.x, f0.y, f1.x, f1.y, f2.x, f2.y, f3.x, f3.y};
#pragma unroll
        for (int t = 0; t < 8; t++) {
            s += hv[t] * sp[q * 8 + t];
            d += hv[t] * dp[q * 8 + t];
        }
    }
    g_alS1[i] = s;
    g_alD1[i] = d;
    // warp-local max per head first (heads cycle over lanes), then one atomic
    float wm = s;
#pragma unroll
    for (int o = 4; o < 32; o <<= 1) wm = fmaxf(wm, __shfl_xor_sync(0xffffffffu, wm, o));
    if ((threadIdx.x >> 2) % 8 == 0) atomicMax(&g_mS1[h], fl_f2u(wm));
}

// ---------------- fused softmax + aggregation, layer 1 (single pass) --------
// shift m = lrelu(globalmax(alS1)+alD1) is an upper bound on the segment max;
// softmax is shift-invariant so the result is exact (no under/overflow: value
// range analysis gives v-m > -20).
__global__ void __launch_bounds__(256) agg1_kernel(const float* __restrict__ b1, int N) {
    int gw = blockIdx.x * 8 + (threadIdx.x >> 5);
    int lane = threadIdx.x & 31;
    if (gw >= N * HEADS) return;
    int n = gw >> 2, hh = gw & 3;
    int start = g_rowptr[n], end = g_rowptr[n + 1];
    float ad = g_alD1[n * HEADS + hh];
    float mg = fl_u2f(g_mS1[hh]) + ad;
    float m = (mg > 0.f) ? mg : 0.2f * mg;

    __shared__ float sw_w[8][32];
    __shared__ int   sw_s[8][32];
    int w = threadIdx.x >> 5;
    float acc0 = 0.f, acc1 = 0.f, ssum = 0.f;
    for (int base = start; base < end; base += 32) {
        int cnt = min(32, end - base);
        float wv = 0.f;
        if (lane < cnt) {
            int s = g_csrsrc[base + lane];
            float v = g_alS1[s * HEADS + hh] + ad;
            v = (v > 0.f) ? v : 0.2f * v;
            wv = __expf(v - m);
            sw_w[w][lane] = wv;
            sw_s[w][lane] = s;
        }
        ssum += wv;
        __syncwarp();
        for (int j = 0; j < cnt; j++) {
            float a = sw_w[w][j];
            __half2 hv2 = *(const __half2*)(g_h1h + (size_t)sw_s[w][j] * 256 +
                                            hh * HID + 2 * lane);
            float2 f = __half22float2(hv2);
            acc0 += a * f.x;
            acc1 += a * f.y;
        }
        __syncwarp();
    }
#pragma unroll
    for (int o = 16; o; o >>= 1) ssum += __shfl_xor_sync(0xffffffffu, ssum, o);
    float inv = 1.0f / (ssum + 1e-16f);
    float2 bv = *(const float2*)(b1 + hh * HID + 2 * lane);
    float r0 = acc0 * inv + bv.x;
    float r1 = acc1 * inv + bv.y;
    r0 = (r0 > 0.f) ? r0 : expm1f(r0);
    r1 = (r1 > 0.f) ? r1 : expm1f(r1);
    *(float2*)(g_out1 + (size_t)n * 256 + hh * HID + 2 * lane) = make_float2(r0, r1);
}

// ---------------- GEMM2 + fused layer-2 logits + global max ----------------
__global__ void __launch_bounds__(256) gemm2_kernel(const float* __restrict__ W,
                                                    const float* __restrict__ as2,
                                                    const float* __restrict__ ad2, int M) {
    __shared__ float Ws[256 * OUTC];  // 40 KB
    int tid = threadIdx.x;
    for (int i = tid; i < (256 * OUTC) / 4; i += 256)
        *(float4*)&Ws[i * 4] = *(const float4*)(W + i * 4);
    __syncthreads();

    int r = tid >> 3;
    int g = tid & 7;
    int grow = blockIdx.x * 32 + r;
    if (grow >= M) return;

    float acc[5] = {0.f, 0.f, 0.f, 0.f, 0.f};
    const float4* ap = (const float4*)(g_out1 + (size_t)grow * 256);
#pragma unroll 4
    for (int k4 = 0; k4 < 64; k4++) {
        float4 a4 = __ldg(&ap[k4]);
        float av[4] = {a4.x, a4.y, a4.z, a4.w};
#pragma unroll
        for (int q = 0; q < 4; q++) {
            const float* wrow = &Ws[(k4 * 4 + q) * OUTC + g * 5];
#pragma unroll
            for (int j = 0; j < 5; j++) acc[j] += av[q] * wrow[j];
        }
    }
    float s = 0.f, d = 0.f;
#pragma unroll
    for (int j = 0; j < 5; j++) {
        g_h2[(size_t)grow * OUTC + g * 5 + j] = acc[j];
        s += acc[j] * __ldg(as2 + g * 5 + j);
        d += acc[j] * __ldg(ad2 + g * 5 + j);
    }
#pragma unroll
    for (int o = 4; o; o >>= 1) {
        s += __shfl_xor_sync(0xffffffffu, s, o);
        d += __shfl_xor_sync(0xffffffffu, d, o);
    }
    if (g == 0) {
        g_alS2[grow] = s;
        g_alD2[grow] = d;
    }
    // block-level max of s, one atomic per block
    __shared__ float smax[256];
    smax[tid] = s;
    __syncthreads();
    for (int o = 128; o; o >>= 1) {
        if (tid < o) smax[tid] = fmaxf(smax[tid], smax[tid + o]);
        __syncthreads();
    }
    if (tid == 0) atomicMax(&g_mS2, fl_f2u(smax[0]));
}

// ---------------- fused softmax + aggregation, layer 2 (single pass) --------
__global__ void __launch_bounds__(256) agg2_kernel(const float* __restrict__ b2,
                                                   float* __restrict__ out, int N) {
    int n = blockIdx.x * 8 + (threadIdx.x >> 5);
    int lane = threadIdx.x & 31;
    if (n >= N) return;
    int start = g_rowptr[n], end = g_rowptr[n + 1];
    float ad = g_alD2[n];
    float mg = fl_u2f(g_mS2) + ad;
    float m = (mg > 0.f) ? mg : 0.2f * mg;

    __shared__ float sw_w[8][32];
    __shared__ int   sw_s[8][32];
    int w = threadIdx.x >> 5;
    float acc0 = 0.f, acc1 = 0.f, ssum = 0.f;
    for (int base = start; base < end; base += 32) {
        int cnt = min(32, end - base);
        float wv = 0.f;
        if (lane < cnt) {
            int s = g_csrsrc[base + lane];
            float v = g_alS2[s] + ad;
            v = (v > 0.f) ? v : 0.2f * v;
            wv = __expf(v - m);
            sw_w[w][lane] = wv;
            sw_s[w][lane] = s;
        }
        ssum += wv;
        __syncwarp();
        if (lane < OUTC / 2) {
            for (int j = 0; j < cnt; j++) {
                float a = sw_w[w][j];
                const float2 hv = *(const float2*)(g_h2 + (size_t)sw_s[w][j] * OUTC +
                                                   2 * lane);
                acc0 += a * hv.x;
                acc1 += a * hv.y;
            }
        }
        __syncwarp();
    }
#pragma unroll
    for (int o = 16; o; o >>= 1) ssum += __shfl_xor_sync(0xffffffffu, ssum, o);
    float inv = 1.0f / (ssum + 1e-16f);
    if (lane < OUTC / 2) {
        float2 bv = *(const float2*)(b2 + 2 * lane);
        *(float2*)(out + (size_t)n * OUTC + 2 * lane) =
            make_float2(acc0 * inv + bv.x, acc1 * inv + bv.y);
    }
}

// ---------------- launch ----------------------------------------------------
extern "C" void kernel_launch(void* const* d_in, const int* in_sizes, int n_in,
                              void* d_out, int out_size) {
    const float* x      = (const float*)d_in[0];
    const int*   ei     = (const int*)d_in[1];
    const float* W1     = (const float*)d_in[2];
    const float* a_src1 = (const float*)d_in[3];
    const float* a_dst1 = (const float*)d_in[4];
    const float* b1     = (const float*)d_in[5];
    const float* W2     = (const float*)d_in[6];
    const float* a_src2 = (const float*)d_in[7];
    const float* a_dst2 = (const float*)d_in[8];
    const float* b2     = (const float*)d_in[9];
    float* out = (float*)d_out;

    int N = in_sizes[0] / 256;   // 50000
    int E = in_sizes[1] / 2;     // 800000
    int Etot = E + N;
    const int* srcE = ei;
    const int* dstE = ei + E;

    // side stream + events for overlapping the CSR chain with the GEMM chain.
    static cudaStream_t sCsr = nullptr;
    static cudaEvent_t evRoot = nullptr, evCsr = nullptr;
    if (sCsr == nullptr) {
        cudaStreamCreateWithFlags(&sCsr, cudaStreamNonBlocking);
        cudaEventCreateWithFlags(&evRoot, cudaEventDisableTiming);
        cudaEventCreateWithFlags(&evCsr, cudaEventDisableTiming);
    }

    // fork: CSR build on side stream
    cudaEventRecord(evRoot, 0);
    cudaStreamWaitEvent(sCsr, evRoot, 0);
    zero_deg_kernel<<<(N + 255) / 256, 256, 0, sCsr>>>(N);
    deg_kernel<<<(Etot + 255) / 256, 256, 0, sCsr>>>(dstE, E, Etot);
    scan_kernel<<<1, 1024, 0, sCsr>>>(N);
    scatter_kernel<<<(Etot + 255) / 256, 256, 0, sCsr>>>(srcE, dstE, E, Etot);
    cudaEventRecord(evCsr, sCsr);

    // main stream: layer-1 linear chain (independent of CSR)
    convx_kernel<<<(MPAD * 64 + 255) / 256, 256>>>(x, N);
    convw_kernel<<<(256 * 256 + 255) / 256, 256>>>(W1);
    mma1_kernel<<<dim3(2, MPAD / 128), 256>>>();
    al1_kernel<<<(N * HEADS + 255) / 256, 256>>>(a_src1, a_dst1, N);

    // join: aggregation needs both chains
    cudaStreamWaitEvent(0, evCsr, 0);
    agg1_kernel<<<(N * HEADS + 7) / 8, 256>>>(b1, N);

    // layer 2
    gemm2_kernel<<<(N + 31) / 32, 256>>>(W2, a_src2, a_dst2, N);
    agg2_kernel<<<(N + 7) / 8, 256>>>(b2, out, N);
}

// round 15
// speedup vs baseline: 1.7025x; 1.0555x over previous
#include <cuda_runtime.h>
#include <cuda_bf16.h>
#include <cuda_fp16.h>
#include <math.h>
#include <stdint.h>

#define NN    50000
#define MPAD  50048        // 391 * 128
#define EE    800000
#define HEADS 4
#define HID   64
#define OUTC  40

// ---------------- scratch (static device globals; no allocations) ----------
__device__ __half g_h1h[(size_t)MPAD * 256];  // layer-1 linear output, fp16
__device__ float g_out1[(size_t)NN * 256];    // layer-1 GAT output after ELU
__device__ float g_h2  [(size_t)NN * OUTC];   // layer-2 linear output
__device__ float g_alS1[NN * HEADS];
__device__ float g_alD1[NN * HEADS];
__device__ float g_alS2[NN];
__device__ float g_alD2[NN];
__device__ unsigned g_mS1[HEADS];             // global max of alS1 per head (flipped uint)
__device__ unsigned g_mS2;                    // global max of alS2
__device__ int   g_deg   [NN];
__device__ int   g_rowptr[NN + 1];
__device__ int   g_cursor[NN];
__device__ int   g_csrsrc[EE + NN];
// bf16x3 split of W1^T (B operand); A (x) is split in-kernel now
__device__ __nv_bfloat16 g_bhi[256 * 256];   // W1^T  [N=256][K=256]
__device__ __nv_bfloat16 g_blo[256 * 256];

// ---------------- helpers ---------------------------------------------------
__device__ __forceinline__ unsigned fl_f2u(float f) {   // order-preserving float->uint
    unsigned u = __float_as_uint(f);
    return (u & 0x80000000u) ? ~u : (u | 0x80000000u);
}
__device__ __forceinline__ float fl_u2f(unsigned u) {
    return __uint_as_float((u & 0x80000000u) ? (u & 0x7fffffffu) : ~u);
}
__device__ __forceinline__ uint32_t smem_u32(const void* p) {
    uint32_t a;
    asm("{ .reg .u64 t; cvta.to.shared.u64 t, %1; cvt.u32.u64 %0, t; }" : "=r"(a) : "l"(p));
    return a;
}
__device__ __forceinline__ void ldsm4(uint32_t* r, uint32_t addr) {
    asm volatile("ldmatrix.sync.aligned.m8n8.x4.shared.b16 {%0,%1,%2,%3}, [%4];"
                 : "=r"(r[0]), "=r"(r[1]), "=r"(r[2]), "=r"(r[3]) : "r"(addr));
}
__device__ __forceinline__ void mma_bf16(float* c, const uint32_t* a, const uint32_t* b) {
    asm volatile(
        "mma.sync.aligned.m16n8k16.row.col.f32.bf16.bf16.f32 "
        "{%0,%1,%2,%3}, {%4,%5,%6,%7}, {%8,%9}, {%0,%1,%2,%3};"
        : "+f"(c[0]), "+f"(c[1]), "+f"(c[2]), "+f"(c[3])
        : "r"(a[0]), "r"(a[1]), "r"(a[2]), "r"(a[3]), "r"(b[0]), "r"(b[1]));
}
__device__ __forceinline__ uint32_t pack_bf2(__nv_bfloat16 a, __nv_bfloat16 b) {
    __nv_bfloat162 t; t.x = a; t.y = b;
    return *(uint32_t*)&t;
}

// ---------------- CSR build ------------------------------------------------
__global__ void zero_deg_kernel(int n) {
    int i = blockIdx.x * blockDim.x + threadIdx.x;
    if (i < n) g_deg[i] = 0;
}

__global__ void deg_kernel(const int* __restrict__ dstE, int E, int Etot) {
    int i = blockIdx.x * blockDim.x + threadIdx.x;
    if (i < Etot) {
        int d = (i < E) ? dstE[i] : (i - E);   // self-loop for i >= E
        atomicAdd(&g_deg[d], 1);
    }
}

__global__ void scan_kernel(int n) {
    __shared__ int sums[1024];
    int tid = threadIdx.x;
    int chunk = (n + 1023) / 1024;
    int start = tid * chunk;
    int end = min(start + chunk, n);
    int s = 0;
    for (int i = start; i < end; i++) s += g_deg[i];
    sums[tid] = s;
    __syncthreads();
    for (int off = 1; off < 1024; off <<= 1) {
        int v = (tid >= off) ? sums[tid - off] : 0;
        __syncthreads();
        sums[tid] += v;
        __syncthreads();
    }
    int base = (tid > 0) ? sums[tid - 1] : 0;
    for (int i = start; i < end; i++) {
        g_rowptr[i] = base;
        g_cursor[i] = base;
        base += g_deg[i];
    }
    if (tid == 1023) g_rowptr[n] = base;
}

__global__ void scatter_kernel(const int* __restrict__ srcE,
                               const int* __restrict__ dstE, int E, int Etot) {
    int i = blockIdx.x * blockDim.x + threadIdx.x;
    if (i < Etot) {
        int s, d;
        if (i < E) { s = srcE[i]; d = dstE[i]; }
        else       { s = d = i - E; }
        int p = atomicAdd(&g_cursor[d], 1);
        g_csrsrc[p] = s;
    }
}

// ---------------- W1 transpose + split (also resets global-max cells) -------
__global__ void convw_kernel(const float* __restrict__ W) {
    int i = blockIdx.x * blockDim.x + threadIdx.x;
    if (i < HEADS) g_mS1[i] = 0u;        // reset before mma1's atomicMax
    if (i == HEADS) g_mS2 = 0u;          // reset before gemm2's atomicMax
    if (i >= 256 * 256) return;
    int n = i >> 8, k = i & 255;
    float v = W[k * 256 + n];
    __nv_bfloat16 h = __float2bfloat16(v);
    g_bhi[i] = h;
    g_blo[i] = __float2bfloat16(v - __bfloat162float(h));
}

// ---------------- fused GEMM1 (mma.sync bf16x3) + x-split + al1 -------------
// CTA = 128 rows x 256 cols (full N). 512 threads = 16 warps (4m x 4n);
// warp tile 32x64 => each n-warp owns exactly one head.
// A (x) loaded fp32, hi/lo bf16 split in-register. Epilogue writes fp16 h1
// and computes alS1/alD1 + per-head global max in place (al1 kernel deleted).
#define SROW 40
#define SM_AHI 0
#define SM_ALO (128 * SROW)
#define SM_BHI (2 * 128 * SROW)
#define SM_BLO (2 * 128 * SROW + 256 * SROW)
#define MMA1_SMEM ((2 * 128 * SROW + 2 * 256 * SROW) * 2)

__global__ void __launch_bounds__(512, 1) mma1_kernel(const float* __restrict__ X,
                                                      const float* __restrict__ as1,
                                                      const float* __restrict__ ad1,
                                                      int M) {
    extern __shared__ __nv_bfloat16 sm[];
    int tid = threadIdx.x;
    int lane = tid & 31, wid = tid >> 5;
    int warp_m = (wid & 3) * 32;
    int warp_n = (wid >> 2) * 64;      // == head * 64
    int rowBase = blockIdx.x * 128;

    uint32_t aHiB = smem_u32(sm + SM_AHI), aLoB = smem_u32(sm + SM_ALO);
    uint32_t bHiB = smem_u32(sm + SM_BHI), bLoB = smem_u32(sm + SM_BLO);

    float acc[2][8][4];
#pragma unroll
    for (int im = 0; im < 2; im++)
#pragma unroll
        for (int jn = 0; jn < 8; jn++)
#pragma unroll
            for (int q = 0; q < 4; q++) acc[im][jn][q] = 0.f;

    // per-thread load indices
    int ar = tid >> 2, acg = (tid & 3) << 3;          // A: row 0..127, col group (8 floats)
    float4 pA0, pA1;
    uint4 pBh[2], pBl[2];

    // prefetch chunk 0
    {
        int grow = rowBase + ar;
        if (grow < M) {
            pA0 = *(const float4*)(X + (size_t)grow * 256 + acg);
            pA1 = *(const float4*)(X + (size_t)grow * 256 + acg + 4);
        } else {
            pA0 = make_float4(0.f, 0.f, 0.f, 0.f);
            pA1 = pA0;
        }
#pragma unroll
        for (int l = 0; l < 2; l++) {
            int v = tid + (l << 9);
            int br = v >> 2, bcg = (v & 3) << 3;
            pBh[l] = *(const uint4*)(g_bhi + (size_t)br * 256 + bcg);
            pBl[l] = *(const uint4*)(g_blo + (size_t)br * 256 + bcg);
        }
    }

    for (int c = 0; c < 8; c++) {
        __syncthreads();
        // store A (convert fp32 -> hi/lo bf16)
        {
            int so = ar * SROW + acg;
            float f[8] = {pA0.x, pA0.y, pA0.z, pA0.w, pA1.x, pA1.y, pA1.z, pA1.w};
            __nv_bfloat16 hi[8], lo[8];
#pragma unroll
            for (int t = 0; t < 8; t++) {
                hi[t] = __float2bfloat16(f[t]);
                lo[t] = __float2bfloat16(f[t] - __bfloat162float(hi[t]));
            }
            uint4 uh, ul;
            uh.x = pack_bf2(hi[0], hi[1]); uh.y = pack_bf2(hi[2], hi[3]);
            uh.z = pack_bf2(hi[4], hi[5]); uh.w = pack_bf2(hi[6], hi[7]);
            ul.x = pack_bf2(lo[0], lo[1]); ul.y = pack_bf2(lo[2], lo[3]);
            ul.z = pack_bf2(lo[4], lo[5]); ul.w = pack_bf2(lo[6], lo[7]);
            *(uint4*)(sm + SM_AHI + so) = uh;
            *(uint4*)(sm + SM_ALO + so) = ul;
        }
        // store B
#pragma unroll
        for (int l = 0; l < 2; l++) {
            int v = tid + (l << 9);
            int br = v >> 2, bcg = (v & 3) << 3;
            int so = br * SROW + bcg;
            *(uint4*)(sm + SM_BHI + so) = pBh[l];
            *(uint4*)(sm + SM_BLO + so) = pBl[l];
        }
        __syncthreads();
        // prefetch next chunk
        if (c < 7) {
            int kk = (c + 1) * 32;
            int grow = rowBase + ar;
            if (grow < M) {
                pA0 = *(const float4*)(X + (size_t)grow * 256 + kk + acg);
                pA1 = *(const float4*)(X + (size_t)grow * 256 + kk + acg + 4);
            } else {
                pA0 = make_float4(0.f, 0.f, 0.f, 0.f);
                pA1 = pA0;
            }
#pragma unroll
            for (int l = 0; l < 2; l++) {
                int v = tid + (l << 9);
                int br = v >> 2, bcg = (v & 3) << 3;
                pBh[l] = *(const uint4*)(g_bhi + (size_t)br * 256 + kk + bcg);
                pBl[l] = *(const uint4*)(g_blo + (size_t)br * 256 + kk + bcg);
            }
        }
        // compute
#pragma unroll
        for (int ks = 0; ks < 2; ks++) {
            uint32_t fAh[2][4], fAl[2][4];
#pragma unroll
            for (int im = 0; im < 2; im++) {
                uint32_t off = ((warp_m + im * 16 + (lane & 15)) * SROW +
                                ks * 16 + (lane >> 4) * 8) * 2;
                ldsm4(fAh[im], aHiB + off);
                ldsm4(fAl[im], aLoB + off);
            }
#pragma unroll
            for (int j2 = 0; j2 < 4; j2++) {
                int s = lane >> 3;
                uint32_t off = ((warp_n + j2 * 16 + ((s >> 1) << 3) + (lane & 7)) * SROW +
                                ks * 16 + ((s & 1) << 3)) * 2;
                uint32_t th[4], tl[4];
                ldsm4(th, bHiB + off);
                ldsm4(tl, bLoB + off);
#pragma unroll
                for (int im = 0; im < 2; im++) {
                    mma_bf16(acc[im][j2 * 2],     fAh[im], th);
                    mma_bf16(acc[im][j2 * 2 + 1], fAh[im], th + 2);
                    mma_bf16(acc[im][j2 * 2],     fAh[im], tl);
                    mma_bf16(acc[im][j2 * 2 + 1], fAh[im], tl + 2);
                    mma_bf16(acc[im][j2 * 2],     fAl[im], th);
                    mma_bf16(acc[im][j2 * 2 + 1], fAl[im], th + 2);
                }
            }
        }
    }

    // ---- epilogue: fp16 h1 stores + fused al1 (per-head dot + global max) --
    int c0 = (lane & 3) * 2;
    float sv[4], dv[4];   // (im, rowhalf) = (0,0),(0,1),(1,0),(1,1)
#pragma unroll
    for (int t = 0; t < 4; t++) { sv[t] = 0.f; dv[t] = 0.f; }

#pragma unroll
    for (int im = 0; im < 2; im++) {
        int row0 = rowBase + warp_m + im * 16 + (lane >> 2);
#pragma unroll
        for (int jn = 0; jn < 8; jn++) {
            int col = warp_n + jn * 8 + c0;
            *(__half2*)(g_h1h + (size_t)row0 * 256 + col) =
                __floats2half2_rn(acc[im][jn][0], acc[im][jn][1]);
            *(__half2*)(g_h1h + (size_t)(row0 + 8) * 256 + col) =
                __floats2half2_rn(acc[im][jn][2], acc[im][jn][3]);
            float ws0 = __ldg(as1 + col), ws1 = __ldg(as1 + col + 1);
            float wd0 = __ldg(ad1 + col), wd1 = __ldg(ad1 + col + 1);
            sv[im * 2]     += acc[im][jn][0] * ws0 + acc[im][jn][1] * ws1;
            sv[im * 2 + 1] += acc[im][jn][2] * ws0 + acc[im][jn][3] * ws1;
            dv[im * 2]     += acc[im][jn][0] * wd0 + acc[im][jn][1] * wd1;
            dv[im * 2 + 1] += acc[im][jn][2] * wd0 + acc[im][jn][3] * wd1;
        }
    }
    // quad reduce (lanes sharing a row differ only in lane&3)
#pragma unroll
    for (int t = 0; t < 4; t++) {
#pragma unroll
        for (int o = 1; o < 4; o <<= 1) {
            sv[t] += __shfl_xor_sync(0xffffffffu, sv[t], o);
            dv[t] += __shfl_xor_sync(0xffffffffu, dv[t], o);
        }
    }
    int head = warp_n >> 6;
    if ((lane & 3) == 0) {
#pragma unroll
        for (int t = 0; t < 4; t++) {
            int row = rowBase + warp_m + (t >> 1) * 16 + (lane >> 2) + (t & 1) * 8;
            if (row < M) {
                g_alS1[row * HEADS + head] = sv[t];
                g_alD1[row * HEADS + head] = dv[t];
            }
        }
    }
    // per-warp global max of alS (pad rows contribute <= their value; max is an
    // upper bound either way, which is all the single-pass softmax needs)
    float mx = fmaxf(fmaxf(sv[0], sv[1]), fmaxf(sv[2], sv[3]));
#pragma unroll
    for (int o = 4; o < 32; o <<= 1) mx = fmaxf(mx, __shfl_xor_sync(0xffffffffu, mx, o));
    if (lane == 0) atomicMax(&g_mS1[head], fl_f2u(mx));
}

// ---------------- fused softmax + aggregation, layer 1 (single pass) --------
__global__ void __launch_bounds__(256) agg1_kernel(const float* __restrict__ b1, int N) {
    int gw = blockIdx.x * 8 + (threadIdx.x >> 5);
    int lane = threadIdx.x & 31;
    if (gw >= N * HEADS) return;
    int n = gw >> 2, hh = gw & 3;
    int start = g_rowptr[n], end = g_rowptr[n + 1];
    float ad = g_alD1[n * HEADS + hh];
    float mg = fl_u2f(g_mS1[hh]) + ad;
    float m = (mg > 0.f) ? mg : 0.2f * mg;

    __shared__ float sw_w[8][32];
    __shared__ int   sw_s[8][32];
    int w = threadIdx.x >> 5;
    float acc0 = 0.f, acc1 = 0.f, ssum = 0.f;
    for (int base = start; base < end; base += 32) {
        int cnt = min(32, end - base);
        float wv = 0.f;
        if (lane < cnt) {
            int s = g_csrsrc[base + lane];
            float v = g_alS1[s * HEADS + hh] + ad;
            v = (v > 0.f) ? v : 0.2f * v;
            wv = __expf(v - m);
            sw_w[w][lane] = wv;
            sw_s[w][lane] = s;
        }
        ssum += wv;
        __syncwarp();
        for (int j = 0; j < cnt; j++) {
            float a = sw_w[w][j];
            __half2 hv2 = *(const __half2*)(g_h1h + (size_t)sw_s[w][j] * 256 +
                                            hh * HID + 2 * lane);
            float2 f = __half22float2(hv2);
            acc0 += a * f.x;
            acc1 += a * f.y;
        }
        __syncwarp();
    }
#pragma unroll
    for (int o = 16; o; o >>= 1) ssum += __shfl_xor_sync(0xffffffffu, ssum, o);
    float inv = 1.0f / (ssum + 1e-16f);
    float2 bv = *(const float2*)(b1 + hh * HID + 2 * lane);
    float r0 = acc0 * inv + bv.x;
    float r1 = acc1 * inv + bv.y;
    r0 = (r0 > 0.f) ? r0 : expm1f(r0);
    r1 = (r1 > 0.f) ? r1 : expm1f(r1);
    *(float2*)(g_out1 + (size_t)n * 256 + hh * HID + 2 * lane) = make_float2(r0, r1);
}

// ---------------- GEMM2 + fused layer-2 logits + global max ----------------
__global__ void __launch_bounds__(256) gemm2_kernel(const float* __restrict__ W,
                                                    const float* __restrict__ as2,
                                                    const float* __restrict__ ad2, int M) {
    __shared__ float Ws[256 * OUTC];  // 40 KB
    int tid = threadIdx.x;
    for (int i = tid; i < (256 * OUTC) / 4; i += 256)
        *(float4*)&Ws[i * 4] = *(const float4*)(W + i * 4);
    __syncthreads();

    int r = tid >> 3;
    int g = tid & 7;
    int grow = blockIdx.x * 32 + r;
    if (grow >= M) return;

    float acc[5] = {0.f, 0.f, 0.f, 0.f, 0.f};
    const float4* ap = (const float4*)(g_out1 + (size_t)grow * 256);
#pragma unroll 4
    for (int k4 = 0; k4 < 64; k4++) {
        float4 a4 = __ldg(&ap[k4]);
        float av[4] = {a4.x, a4.y, a4.z, a4.w};
#pragma unroll
        for (int q = 0; q < 4; q++) {
            const float* wrow = &Ws[(k4 * 4 + q) * OUTC + g * 5];
#pragma unroll
            for (int j = 0; j < 5; j++) acc[j] += av[q] * wrow[j];
        }
    }
    float s = 0.f, d = 0.f;
#pragma unroll
    for (int j = 0; j < 5; j++) {
        g_h2[(size_t)grow * OUTC + g * 5 + j] = acc[j];
        s += acc[j] * __ldg(as2 + g * 5 + j);
        d += acc[j] * __ldg(ad2 + g * 5 + j);
    }
#pragma unroll
    for (int o = 4; o; o >>= 1) {
        s += __shfl_xor_sync(0xffffffffu, s, o);
        d += __shfl_xor_sync(0xffffffffu, d, o);
    }
    if (g == 0) {
        g_alS2[grow] = s;
        g_alD2[grow] = d;
    }
    __shared__ float smax[256];
    smax[tid] = s;
    __syncthreads();
    for (int o = 128; o; o >>= 1) {
        if (tid < o) smax[tid] = fmaxf(smax[tid], smax[tid + o]);
        __syncthreads();
    }
    if (tid == 0) atomicMax(&g_mS2, fl_f2u(smax[0]));
}

// ---------------- fused softmax + aggregation, layer 2 (single pass) --------
__global__ void __launch_bounds__(256) agg2_kernel(const float* __restrict__ b2,
                                                   float* __restrict__ out, int N) {
    int n = blockIdx.x * 8 + (threadIdx.x >> 5);
    int lane = threadIdx.x & 31;
    if (n >= N) return;
    int start = g_rowptr[n], end = g_rowptr[n + 1];
    float ad = g_alD2[n];
    float mg = fl_u2f(g_mS2) + ad;
    float m = (mg > 0.f) ? mg : 0.2f * mg;

    __shared__ float sw_w[8][32];
    __shared__ int   sw_s[8][32];
    int w = threadIdx.x >> 5;
    float acc0 = 0.f, acc1 = 0.f, ssum = 0.f;
    for (int base = start; base < end; base += 32) {
        int cnt = min(32, end - base);
        float wv = 0.f;
        if (lane < cnt) {
            int s = g_csrsrc[base + lane];
            float v = g_alS2[s] + ad;
            v = (v > 0.f) ? v : 0.2f * v;
            wv = __expf(v - m);
            sw_w[w][lane] = wv;
            sw_s[w][lane] = s;
        }
        ssum += wv;
        __syncwarp();
        if (lane < OUTC / 2) {
            for (int j = 0; j < cnt; j++) {
                float a = sw_w[w][j];
                const float2 hv = *(const float2*)(g_h2 + (size_t)sw_s[w][j] * OUTC +
                                                   2 * lane);
                acc0 += a * hv.x;
                acc1 += a * hv.y;
            }
        }
        __syncwarp();
    }
#pragma unroll
    for (int o = 16; o; o >>= 1) ssum += __shfl_xor_sync(0xffffffffu, ssum, o);
    float inv = 1.0f / (ssum + 1e-16f);
    if (lane < OUTC / 2) {
        float2 bv = *(const float2*)(b2 + 2 * lane);
        *(float2*)(out + (size_t)n * OUTC + 2 * lane) =
            make_float2(acc0 * inv + bv.x, acc1 * inv + bv.y);
    }
}

// ---------------- launch ----------------------------------------------------
extern "C" void kernel_launch(void* const* d_in, const int* in_sizes, int n_in,
                              void* d_out, int out_size) {
    const float* x      = (const float*)d_in[0];
    const int*   ei     = (const int*)d_in[1];
    const float* W1     = (const float*)d_in[2];
    const float* a_src1 = (const float*)d_in[3];
    const float* a_dst1 = (const float*)d_in[4];
    const float* b1     = (const float*)d_in[5];
    const float* W2     = (const float*)d_in[6];
    const float* a_src2 = (const float*)d_in[7];
    const float* a_dst2 = (const float*)d_in[8];
    const float* b2     = (const float*)d_in[9];
    float* out = (float*)d_out;

    int N = in_sizes[0] / 256;   // 50000
    int E = in_sizes[1] / 2;     // 800000
    int Etot = E + N;
    const int* srcE = ei;
    const int* dstE = ei + E;

    // one-time resources (no device memory): side stream, events, smem opt-in
    static cudaStream_t sCsr = nullptr;
    static cudaEvent_t evRoot = nullptr, evCsr = nullptr;
    if (sCsr == nullptr) {
        cudaStreamCreateWithFlags(&sCsr, cudaStreamNonBlocking);
        cudaEventCreateWithFlags(&evRoot, cudaEventDisableTiming);
        cudaEventCreateWithFlags(&evCsr, cudaEventDisableTiming);
        cudaFuncSetAttribute(mma1_kernel,
                             cudaFuncAttributeMaxDynamicSharedMemorySize, MMA1_SMEM);
    }

    // fork: CSR build on side stream
    cudaEventRecord(evRoot, 0);
    cudaStreamWaitEvent(sCsr, evRoot, 0);
    zero_deg_kernel<<<(N + 255) / 256, 256, 0, sCsr>>>(N);
    deg_kernel<<<(Etot + 255) / 256, 256, 0, sCsr>>>(dstE, E, Etot);
    scan_kernel<<<1, 1024, 0, sCsr>>>(N);
    scatter_kernel<<<(Etot + 255) / 256, 256, 0, sCsr>>>(srcE, dstE, E, Etot);
    cudaEventRecord(evCsr, sCsr);

    // main stream: fused layer-1 linear chain
    convw_kernel<<<(256 * 256 + 255) / 256, 256>>>(W1);
    mma1_kernel<<<MPAD / 128, 512, MMA1_SMEM>>>(x, a_src1, a_dst1, N);

    // join: aggregation needs both chains
    cudaStreamWaitEvent(0, evCsr, 0);
    agg1_kernel<<<(N * HEADS + 7) / 8, 256>>>(b1, N);

    // layer 2
    gemm2_kernel<<<(N + 31) / 32, 256>>>(W2, a_src2, a_dst2, N);
    agg2_kernel<<<(N + 7) / 8, 256>>>(b2, out, N);
}

// round 16
// speedup vs baseline: 2.0692x; 1.2154x over previous
#include <cuda_runtime.h>
#include <cuda_bf16.h>
#include <cuda_fp16.h>
#include <math.h>
#include <stdint.h>

#define NN    50000
#define MPAD  50048        // 391 * 128
#define EE    800000
#define HEADS 4
#define HID   64
#define OUTC  40

// ---------------- scratch (static device globals; no allocations) ----------
__device__ __half g_h1h [(size_t)MPAD * 256];  // layer-1 linear output, fp16
__device__ __half g_out1h[(size_t)NN * 256];   // layer-1 GAT output after ELU, fp16
__device__ __half g_h2h [(size_t)NN * OUTC];   // layer-2 linear output, fp16
__device__ float g_alS1[NN * HEADS];
__device__ float g_alD1[NN * HEADS];
__device__ float g_alS2[NN];
__device__ float g_alD2[NN];
__device__ unsigned g_mS1[HEADS];              // global max of alS1 per head (flipped uint)
__device__ unsigned g_mS2;                     // global max of alS2
__device__ int   g_deg   [NN];
__device__ int   g_rowptr[NN + 1];
__device__ int   g_cursor[NN];
__device__ int   g_csrsrc[EE + NN];
// bf16x3 split of W1^T (B operand); A (x) is split in-kernel
__device__ __nv_bfloat16 g_bhi[256 * 256];     // W1^T  [N=256][K=256]
__device__ __nv_bfloat16 g_blo[256 * 256];

// ---------------- helpers ---------------------------------------------------
__device__ __forceinline__ unsigned fl_f2u(float f) {   // order-preserving float->uint
    unsigned u = __float_as_uint(f);
    return (u & 0x80000000u) ? ~u : (u | 0x80000000u);
}
__device__ __forceinline__ float fl_u2f(unsigned u) {
    return __uint_as_float((u & 0x80000000u) ? (u & 0x7fffffffu) : ~u);
}
__device__ __forceinline__ uint32_t smem_u32(const void* p) {
    uint32_t a;
    asm("{ .reg .u64 t; cvta.to.shared.u64 t, %1; cvt.u32.u64 %0, t; }" : "=r"(a) : "l"(p));
    return a;
}
__device__ __forceinline__ void ldsm4(uint32_t* r, uint32_t addr) {
    asm volatile("ldmatrix.sync.aligned.m8n8.x4.shared.b16 {%0,%1,%2,%3}, [%4];"
                 : "=r"(r[0]), "=r"(r[1]), "=r"(r[2]), "=r"(r[3]) : "r"(addr));
}
__device__ __forceinline__ void mma_bf16(float* c, const uint32_t* a, const uint32_t* b) {
    asm volatile(
        "mma.sync.aligned.m16n8k16.row.col.f32.bf16.bf16.f32 "
        "{%0,%1,%2,%3}, {%4,%5,%6,%7}, {%8,%9}, {%0,%1,%2,%3};"
        : "+f"(c[0]), "+f"(c[1]), "+f"(c[2]), "+f"(c[3])
        : "r"(a[0]), "r"(a[1]), "r"(a[2]), "r"(a[3]), "r"(b[0]), "r"(b[1]));
}
__device__ __forceinline__ uint32_t pack_bf2(__nv_bfloat16 a, __nv_bfloat16 b) {
    __nv_bfloat162 t; t.x = a; t.y = b;
    return *(uint32_t*)&t;
}
__device__ __forceinline__ uint32_t h2_bits(__half2 h) { return *(uint32_t*)&h; }

// ---------------- CSR build ------------------------------------------------
__global__ void zero_deg_kernel(int n) {
    int i = blockIdx.x * blockDim.x + threadIdx.x;
    if (i < n) g_deg[i] = 0;
}

__global__ void deg_kernel(const int* __restrict__ dstE, int E, int Etot) {
    int i = blockIdx.x * blockDim.x + threadIdx.x;
    if (i < Etot) {
        int d = (i < E) ? dstE[i] : (i - E);   // self-loop for i >= E
        atomicAdd(&g_deg[d], 1);
    }
}

__global__ void scan_kernel(int n) {
    __shared__ int sums[1024];
    int tid = threadIdx.x;
    int chunk = (n + 1023) / 1024;
    int start = tid * chunk;
    int end = min(start + chunk, n);
    int s = 0;
    for (int i = start; i < end; i++) s += g_deg[i];
    sums[tid] = s;
    __syncthreads();
    for (int off = 1; off < 1024; off <<= 1) {
        int v = (tid >= off) ? sums[tid - off] : 0;
        __syncthreads();
        sums[tid] += v;
        __syncthreads();
    }
    int base = (tid > 0) ? sums[tid - 1] : 0;
    for (int i = start; i < end; i++) {
        g_rowptr[i] = base;
        g_cursor[i] = base;
        base += g_deg[i];
    }
    if (tid == 1023) g_rowptr[n] = base;
}

__global__ void scatter_kernel(const int* __restrict__ srcE,
                               const int* __restrict__ dstE, int E, int Etot) {
    int i = blockIdx.x * blockDim.x + threadIdx.x;
    if (i < Etot) {
        int s, d;
        if (i < E) { s = srcE[i]; d = dstE[i]; }
        else       { s = d = i - E; }
        int p = atomicAdd(&g_cursor[d], 1);
        g_csrsrc[p] = s;
    }
}

// ---------------- W1 transpose + split (also resets global-max cells) -------
__global__ void convw_kernel(const float* __restrict__ W) {
    int i = blockIdx.x * blockDim.x + threadIdx.x;
    if (i < HEADS) g_mS1[i] = 0u;        // reset before mma1's atomicMax
    if (i == HEADS) g_mS2 = 0u;          // reset before gemm2's atomicMax
    if (i >= 256 * 256) return;
    int n = i >> 8, k = i & 255;
    float v = W[k * 256 + n];
    __nv_bfloat16 h = __float2bfloat16(v);
    g_bhi[i] = h;
    g_blo[i] = __float2bfloat16(v - __bfloat162float(h));
}

// ---------------- fused GEMM1 (mma.sync bf16x3) + x-split + al1 -------------
#define SROW 40
#define SM_AHI 0
#define SM_ALO (128 * SROW)
#define SM_BHI (2 * 128 * SROW)
#define SM_BLO (2 * 128 * SROW + 256 * SROW)
#define MMA1_SMEM ((2 * 128 * SROW + 2 * 256 * SROW) * 2)

__global__ void __launch_bounds__(512, 1) mma1_kernel(const float* __restrict__ X,
                                                      const float* __restrict__ as1,
                                                      const float* __restrict__ ad1,
                                                      int M) {
    extern __shared__ __nv_bfloat16 sm[];
    int tid = threadIdx.x;
    int lane = tid & 31, wid = tid >> 5;
    int warp_m = (wid & 3) * 32;
    int warp_n = (wid >> 2) * 64;      // == head * 64
    int rowBase = blockIdx.x * 128;

    uint32_t aHiB = smem_u32(sm + SM_AHI), aLoB = smem_u32(sm + SM_ALO);
    uint32_t bHiB = smem_u32(sm + SM_BHI), bLoB = smem_u32(sm + SM_BLO);

    float acc[2][8][4];
#pragma unroll
    for (int im = 0; im < 2; im++)
#pragma unroll
        for (int jn = 0; jn < 8; jn++)
#pragma unroll
            for (int q = 0; q < 4; q++) acc[im][jn][q] = 0.f;

    int ar = tid >> 2, acg = (tid & 3) << 3;
    float4 pA0, pA1;
    uint4 pBh[2], pBl[2];

    {
        int grow = rowBase + ar;
        if (grow < M) {
            pA0 = *(const float4*)(X + (size_t)grow * 256 + acg);
            pA1 = *(const float4*)(X + (size_t)grow * 256 + acg + 4);
        } else {
            pA0 = make_float4(0.f, 0.f, 0.f, 0.f);
            pA1 = pA0;
        }
#pragma unroll
        for (int l = 0; l < 2; l++) {
            int v = tid + (l << 9);
            int br = v >> 2, bcg = (v & 3) << 3;
            pBh[l] = *(const uint4*)(g_bhi + (size_t)br * 256 + bcg);
            pBl[l] = *(const uint4*)(g_blo + (size_t)br * 256 + bcg);
        }
    }

    for (int c = 0; c < 8; c++) {
        __syncthreads();
        {
            int so = ar * SROW + acg;
            float f[8] = {pA0.x, pA0.y, pA0.z, pA0.w, pA1.x, pA1.y, pA1.z, pA1.w};
            __nv_bfloat16 hi[8], lo[8];
#pragma unroll
            for (int t = 0; t < 8; t++) {
                hi[t] = __float2bfloat16(f[t]);
                lo[t] = __float2bfloat16(f[t] - __bfloat162float(hi[t]));
            }
            uint4 uh, ul;
            uh.x = pack_bf2(hi[0], hi[1]); uh.y = pack_bf2(hi[2], hi[3]);
            uh.z = pack_bf2(hi[4], hi[5]); uh.w = pack_bf2(hi[6], hi[7]);
            ul.x = pack_bf2(lo[0], lo[1]); ul.y = pack_bf2(lo[2], lo[3]);
            ul.z = pack_bf2(lo[4], lo[5]); ul.w = pack_bf2(lo[6], lo[7]);
            *(uint4*)(sm + SM_AHI + so) = uh;
            *(uint4*)(sm + SM_ALO + so) = ul;
        }
#pragma unroll
        for (int l = 0; l < 2; l++) {
            int v = tid + (l << 9);
            int br = v >> 2, bcg = (v & 3) << 3;
            int so = br * SROW + bcg;
            *(uint4*)(sm + SM_BHI + so) = pBh[l];
            *(uint4*)(sm + SM_BLO + so) = pBl[l];
        }
        __syncthreads();
        if (c < 7) {
            int kk = (c + 1) * 32;
            int grow = rowBase + ar;
            if (grow < M) {
                pA0 = *(const float4*)(X + (size_t)grow * 256 + kk + acg);
                pA1 = *(const float4*)(X + (size_t)grow * 256 + kk + acg + 4);
            } else {
                pA0 = make_float4(0.f, 0.f, 0.f, 0.f);
                pA1 = pA0;
            }
#pragma unroll
            for (int l = 0; l < 2; l++) {
                int v = tid + (l << 9);
                int br = v >> 2, bcg = (v & 3) << 3;
                pBh[l] = *(const uint4*)(g_bhi + (size_t)br * 256 + kk + bcg);
                pBl[l] = *(const uint4*)(g_blo + (size_t)br * 256 + kk + bcg);
            }
        }
#pragma unroll
        for (int ks = 0; ks < 2; ks++) {
            uint32_t fAh[2][4], fAl[2][4];
#pragma unroll
            for (int im = 0; im < 2; im++) {
                uint32_t off = ((warp_m + im * 16 + (lane & 15)) * SROW +
                                ks * 16 + (lane >> 4) * 8) * 2;
                ldsm4(fAh[im], aHiB + off);
                ldsm4(fAl[im], aLoB + off);
            }
#pragma unroll
            for (int j2 = 0; j2 < 4; j2++) {
                int s = lane >> 3;
                uint32_t off = ((warp_n + j2 * 16 + ((s >> 1) << 3) + (lane & 7)) * SROW +
                                ks * 16 + ((s & 1) << 3)) * 2;
                uint32_t th[4], tl[4];
                ldsm4(th, bHiB + off);
                ldsm4(tl, bLoB + off);
#pragma unroll
                for (int im = 0; im < 2; im++) {
                    mma_bf16(acc[im][j2 * 2],     fAh[im], th);
                    mma_bf16(acc[im][j2 * 2 + 1], fAh[im], th + 2);
                    mma_bf16(acc[im][j2 * 2],     fAh[im], tl);
                    mma_bf16(acc[im][j2 * 2 + 1], fAh[im], tl + 2);
                    mma_bf16(acc[im][j2 * 2],     fAl[im], th);
                    mma_bf16(acc[im][j2 * 2 + 1], fAl[im], th + 2);
                }
            }
        }
    }

    // ---- epilogue: fp16 h1 stores + fused al1 (per-head dot + global max) --
    int c0 = (lane & 3) * 2;
    float sv[4], dv[4];
#pragma unroll
    for (int t = 0; t < 4; t++) { sv[t] = 0.f; dv[t] = 0.f; }

#pragma unroll
    for (int im = 0; im < 2; im++) {
        int row0 = rowBase + warp_m + im * 16 + (lane >> 2);
#pragma unroll
        for (int jn = 0; jn < 8; jn++) {
            int col = warp_n + jn * 8 + c0;
            *(__half2*)(g_h1h + (size_t)row0 * 256 + col) =
                __floats2half2_rn(acc[im][jn][0], acc[im][jn][1]);
            *(__half2*)(g_h1h + (size_t)(row0 + 8) * 256 + col) =
                __floats2half2_rn(acc[im][jn][2], acc[im][jn][3]);
            float ws0 = __ldg(as1 + col), ws1 = __ldg(as1 + col + 1);
            float wd0 = __ldg(ad1 + col), wd1 = __ldg(ad1 + col + 1);
            sv[im * 2]     += acc[im][jn][0] * ws0 + acc[im][jn][1] * ws1;
            sv[im * 2 + 1] += acc[im][jn][2] * ws0 + acc[im][jn][3] * ws1;
            dv[im * 2]     += acc[im][jn][0] * wd0 + acc[im][jn][1] * wd1;
            dv[im * 2 + 1] += acc[im][jn][2] * wd0 + acc[im][jn][3] * wd1;
        }
    }
#pragma unroll
    for (int t = 0; t < 4; t++) {
#pragma unroll
        for (int o = 1; o < 4; o <<= 1) {
            sv[t] += __shfl_xor_sync(0xffffffffu, sv[t], o);
            dv[t] += __shfl_xor_sync(0xffffffffu, dv[t], o);
        }
    }
    int head = warp_n >> 6;
    if ((lane & 3) == 0) {
#pragma unroll
        for (int t = 0; t < 4; t++) {
            int row = rowBase + warp_m + (t >> 1) * 16 + (lane >> 2) + (t & 1) * 8;
            if (row < M) {
                g_alS1[row * HEADS + head] = sv[t];
                g_alD1[row * HEADS + head] = dv[t];
            }
        }
    }
    float mx = fmaxf(fmaxf(sv[0], sv[1]), fmaxf(sv[2], sv[3]));
#pragma unroll
    for (int o = 4; o < 32; o <<= 1) mx = fmaxf(mx, __shfl_xor_sync(0xffffffffu, mx, o));
    if (lane == 0) atomicMax(&g_mS1[head], fl_f2u(mx));
}

// ---------------- fused softmax + aggregation, layer 1 ---------------------
// ONE warp per node, all 4 heads. Lane owns 8 contiguous channels
// (head = lane>>3). Per edge: 1 csrsrc read, 1 float4 alS gather (all heads),
// 4 exps, then 32 coalesced LDG.128 row loads.
__global__ void __launch_bounds__(256) agg1_kernel(const float* __restrict__ b1, int N) {
    int n = blockIdx.x * 8 + (threadIdx.x >> 5);
    int lane = threadIdx.x & 31;
    if (n >= N) return;
    int start = g_rowptr[n], end = g_rowptr[n + 1];
    int myh = lane >> 3;

    float4 ad4 = *(const float4*)(g_alD1 + n * 4);
    float adv[4] = {ad4.x, ad4.y, ad4.z, ad4.w};
    float m4[4];
#pragma unroll
    for (int h = 0; h < 4; h++) {
        float mg = fl_u2f(g_mS1[h]) + adv[h];
        m4[h] = (mg > 0.f) ? mg : 0.2f * mg;
    }

    __shared__ float4 sw_w[8][32];
    __shared__ int    sw_s[8][32];
    int w = threadIdx.x >> 5;
    float acc[8];
#pragma unroll
    for (int t = 0; t < 8; t++) acc[t] = 0.f;
    float sum0 = 0.f, sum1 = 0.f, sum2 = 0.f, sum3 = 0.f;

    for (int base = start; base < end; base += 32) {
        int cnt = min(32, end - base);
        if (lane < cnt) {
            int s = g_csrsrc[base + lane];
            float4 as4 = *(const float4*)(g_alS1 + s * 4);
            float v0 = as4.x + adv[0]; v0 = (v0 > 0.f) ? v0 : 0.2f * v0;
            float v1 = as4.y + adv[1]; v1 = (v1 > 0.f) ? v1 : 0.2f * v1;
            float v2 = as4.z + adv[2]; v2 = (v2 > 0.f) ? v2 : 0.2f * v2;
            float v3 = as4.w + adv[3]; v3 = (v3 > 0.f) ? v3 : 0.2f * v3;
            float w0 = __expf(v0 - m4[0]);
            float w1 = __expf(v1 - m4[1]);
            float w2 = __expf(v2 - m4[2]);
            float w3 = __expf(v3 - m4[3]);
            sw_w[w][lane] = make_float4(w0, w1, w2, w3);
            sw_s[w][lane] = s;
            sum0 += w0; sum1 += w1; sum2 += w2; sum3 += w3;
        }
        __syncwarp();
        for (int j = 0; j < cnt; j++) {
            float aw = ((const float*)&sw_w[w][j])[myh];
            uint4 hv = *(const uint4*)(g_h1h + (size_t)sw_s[w][j] * 256 + 8 * lane);
            float2 f0 = __half22float2(*(const __half2*)&hv.x);
            float2 f1 = __half22float2(*(const __half2*)&hv.y);
            float2 f2 = __half22float2(*(const __half2*)&hv.z);
            float2 f3 = __half22float2(*(const __half2*)&hv.w);
            acc[0] += aw * f0.x; acc[1] += aw * f0.y;
            acc[2] += aw * f1.x; acc[3] += aw * f1.y;
            acc[4] += aw * f2.x; acc[5] += aw * f2.y;
            acc[6] += aw * f3.x; acc[7] += aw * f3.y;
        }
        __syncwarp();
    }
#pragma unroll
    for (int o = 16; o; o >>= 1) {
        sum0 += __shfl_xor_sync(0xffffffffu, sum0, o);
        sum1 += __shfl_xor_sync(0xffffffffu, sum1, o);
        sum2 += __shfl_xor_sync(0xffffffffu, sum2, o);
        sum3 += __shfl_xor_sync(0xffffffffu, sum3, o);
    }
    float sums[4] = {sum0, sum1, sum2, sum3};
    float inv = 1.0f / (sums[myh] + 1e-16f);

    float4 bA = *(const float4*)(b1 + 8 * lane);
    float4 bB = *(const float4*)(b1 + 8 * lane + 4);
    float r[8];
    r[0] = acc[0] * inv + bA.x; r[1] = acc[1] * inv + bA.y;
    r[2] = acc[2] * inv + bA.z; r[3] = acc[3] * inv + bA.w;
    r[4] = acc[4] * inv + bB.x; r[5] = acc[5] * inv + bB.y;
    r[6] = acc[6] * inv + bB.z; r[7] = acc[7] * inv + bB.w;
#pragma unroll
    for (int t = 0; t < 8; t++) r[t] = (r[t] > 0.f) ? r[t] : expm1f(r[t]);
    uint4 o;
    o.x = h2_bits(__floats2half2_rn(r[0], r[1]));
    o.y = h2_bits(__floats2half2_rn(r[2], r[3]));
    o.z = h2_bits(__floats2half2_rn(r[4], r[5]));
    o.w = h2_bits(__floats2half2_rn(r[6], r[7]));
    *(uint4*)(g_out1h + (size_t)n * 256 + 8 * lane) = o;
}

// ---------------- GEMM2 (fp16 in) + fused layer-2 logits + global max ------
__global__ void __launch_bounds__(256) gemm2_kernel(const float* __restrict__ W,
                                                    const float* __restrict__ as2,
                                                    const float* __restrict__ ad2, int M) {
    __shared__ float Ws[256 * OUTC];  // 40 KB
    int tid = threadIdx.x;
    for (int i = tid; i < (256 * OUTC) / 4; i += 256)
        *(float4*)&Ws[i * 4] = *(const float4*)(W + i * 4);
    __syncthreads();

    int r = tid >> 3;
    int g = tid & 7;
    int grow = blockIdx.x * 32 + r;
    if (grow >= M) return;

    float acc[5] = {0.f, 0.f, 0.f, 0.f, 0.f};
    const uint4* ap = (const uint4*)(g_out1h + (size_t)grow * 256);  // 8 halves each
#pragma unroll 4
    for (int k8 = 0; k8 < 32; k8++) {
        uint4 u = __ldg(&ap[k8]);
        float2 f0 = __half22float2(*(const __half2*)&u.x);
        float2 f1 = __half22float2(*(const __half2*)&u.y);
        float2 f2 = __half22float2(*(const __half2*)&u.z);
        float2 f3 = __half22float2(*(const __half2*)&u.w);
        float av[8] = {f0.x, f0.y, f1.x, f1.y, f2.x, f2.y, f3.x, f3.y};
#pragma unroll
        for (int q = 0; q < 8; q++) {
            const float* wrow = &Ws[(k8 * 8 + q) * OUTC + g * 5];
#pragma unroll
            for (int j = 0; j < 5; j++) acc[j] += av[q] * wrow[j];
        }
    }
    float s = 0.f, d = 0.f;
#pragma unroll
    for (int j = 0; j < 5; j++) {
        g_h2h[(size_t)grow * OUTC + g * 5 + j] = __float2half_rn(acc[j]);
        s += acc[j] * __ldg(as2 + g * 5 + j);
        d += acc[j] * __ldg(ad2 + g * 5 + j);
    }
#pragma unroll
    for (int o = 4; o; o >>= 1) {
        s += __shfl_xor_sync(0xffffffffu, s, o);
        d += __shfl_xor_sync(0xffffffffu, d, o);
    }
    if (g == 0) {
        g_alS2[grow] = s;
        g_alD2[grow] = d;
    }
    __shared__ float smax[256];
    smax[tid] = s;
    __syncthreads();
    for (int o = 128; o; o >>= 1) {
        if (tid < o) smax[tid] = fmaxf(smax[tid], smax[tid + o]);
        __syncthreads();
    }
    if (tid == 0) atomicMax(&g_mS2, fl_f2u(smax[0]));
}

// ---------------- fused softmax + aggregation, layer 2 (fp16 gather) --------
__global__ void __launch_bounds__(256) agg2_kernel(const float* __restrict__ b2,
                                                   float* __restrict__ out, int N) {
    int n = blockIdx.x * 8 + (threadIdx.x >> 5);
    int lane = threadIdx.x & 31;
    if (n >= N) return;
    int start = g_rowptr[n], end = g_rowptr[n + 1];
    float ad = g_alD2[n];
    float mg = fl_u2f(g_mS2) + ad;
    float m = (mg > 0.f) ? mg : 0.2f * mg;

    __shared__ float sw_w[8][32];
    __shared__ int   sw_s[8][32];
    int w = threadIdx.x >> 5;
    float acc0 = 0.f, acc1 = 0.f, ssum = 0.f;
    for (int base = start; base < end; base += 32) {
        int cnt = min(32, end - base);
        float wv = 0.f;
        if (lane < cnt) {
            int s = g_csrsrc[base + lane];
            float v = g_alS2[s] + ad;
            v = (v > 0.f) ? v : 0.2f * v;
            wv = __expf(v - m);
            sw_w[w][lane] = wv;
            sw_s[w][lane] = s;
        }
        ssum += wv;
        __syncwarp();
        if (lane < OUTC / 2) {
            for (int j = 0; j < cnt; j++) {
                float a = sw_w[w][j];
                __half2 hv2 = *(const __half2*)(g_h2h + (size_t)sw_s[w][j] * OUTC +
                                                2 * lane);
                float2 f = __half22float2(hv2);
                acc0 += a * f.x;
                acc1 += a * f.y;
            }
        }
        __syncwarp();
    }
#pragma unroll
    for (int o = 16; o; o >>= 1) ssum += __shfl_xor_sync(0xffffffffu, ssum, o);
    float inv = 1.0f / (ssum + 1e-16f);
    if (lane < OUTC / 2) {
        float2 bv = *(const float2*)(b2 + 2 * lane);
        *(float2*)(out + (size_t)n * OUTC + 2 * lane) =
            make_float2(acc0 * inv + bv.x, acc1 * inv + bv.y);
    }
}

// ---------------- launch ----------------------------------------------------
extern "C" void kernel_launch(void* const* d_in, const int* in_sizes, int n_in,
                              void* d_out, int out_size) {
    const float* x      = (const float*)d_in[0];
    const int*   ei     = (const int*)d_in[1];
    const float* W1     = (const float*)d_in[2];
    const float* a_src1 = (const float*)d_in[3];
    const float* a_dst1 = (const float*)d_in[4];
    const float* b1     = (const float*)d_in[5];
    const float* W2     = (const float*)d_in[6];
    const float* a_src2 = (const float*)d_in[7];
    const float* a_dst2 = (const float*)d_in[8];
    const float* b2     = (const float*)d_in[9];
    float* out = (float*)d_out;

    int N = in_sizes[0] / 256;   // 50000
    int E = in_sizes[1] / 2;     // 800000
    int Etot = E + N;
    const int* srcE = ei;
    const int* dstE = ei + E;

    // one-time resources (no device memory): side stream, events, smem opt-in
    static cudaStream_t sCsr = nullptr;
    static cudaEvent_t evRoot = nullptr, evCsr = nullptr;
    if (sCsr == nullptr) {
        cudaStreamCreateWithFlags(&sCsr, cudaStreamNonBlocking);
        cudaEventCreateWithFlags(&evRoot, cudaEventDisableTiming);
        cudaEventCreateWithFlags(&evCsr, cudaEventDisableTiming);
        cudaFuncSetAttribute(mma1_kernel,
                             cudaFuncAttributeMaxDynamicSharedMemorySize, MMA1_SMEM);
    }

    // fork: CSR build on side stream
    cudaEventRecord(evRoot, 0);
    cudaStreamWaitEvent(sCsr, evRoot, 0);
    zero_deg_kernel<<<(N + 255) / 256, 256, 0, sCsr>>>(N);
    deg_kernel<<<(Etot + 255) / 256, 256, 0, sCsr>>>(dstE, E, Etot);
    scan_kernel<<<1, 1024, 0, sCsr>>>(N);
    scatter_kernel<<<(Etot + 255) / 256, 256, 0, sCsr>>>(srcE, dstE, E, Etot);
    cudaEventRecord(evCsr, sCsr);

    // main stream: fused layer-1 linear chain
    convw_kernel<<<(256 * 256 + 255) / 256, 256>>>(W1);
    mma1_kernel<<<MPAD / 128, 512, MMA1_SMEM>>>(x, a_src1, a_dst1, N);

    // join: aggregation needs both chains
    cudaStreamWaitEvent(0, evCsr, 0);
    agg1_kernel<<<(N + 7) / 8, 256>>>(b1, N);

    // layer 2
    gemm2_kernel<<<(N + 31) / 32, 256>>>(W2, a_src2, a_dst2, N);
    agg2_kernel<<<(N + 7) / 8, 256>>>(b2, out, N);
}